// round 1
// baseline (speedup 1.0000x reference)
#include <cuda_runtime.h>
#include <cuda_bf16.h>

// ---------------------------------------------------------------------------
// DRA_C: decoder [8,256,224,224], trans [8,196,960] -> out [8,128,224,224]
// Pipeline:
//  K0  zero scratch (stats, dl accumulator)
//  K1  mask conv1x1 GEMM (t1 = W_m @ decoder + b) + per-channel sum/sumsq
//  K2  patch-embed GEMM (split-K, atomic accumulate into dl[n][co])
//  K3  BN1 finalize -> (a1, b1') affine
//  K4  k,v = trans @ wk/wv
//  Kq  q = (dl + pe_b) @ wq
//  K5  sim = q^T k per batch + instance-norm stats
//  K5c softmax rows
//  K5b o = P @ v, o2 = o @ wo
//  K6  y = rec_w @ o2 + rec_b     (stays at 14x14: upsample commutes w/ 1x1 conv)
//  K7  BN2 stats over small map (== stats over upsampled) -> (a2, b2')
//  K8  out = relu(a1*t1+b1') * relu(a2*y[..,y/16,x/16]+b2')
// ---------------------------------------------------------------------------

#define S2 50176            // 224*224
#define NPIX_TOT 401408     // 8*224*224
#define NTOK 1568           // 8*196

// ------------------------- device scratch (static) -------------------------
__device__ float g_t1[8 * 128 * 224 * 224];   // 205 MB
__device__ float g_dl[NTOK * 256];
__device__ float g_stats1[256];
__device__ float g_q[NTOK * 128];
__device__ float g_k[NTOK * 128];
__device__ float g_v[NTOK * 128];
__device__ float g_sim[8 * 128 * 128];
__device__ float g_inorm[16];
__device__ float g_p[8 * 128 * 128];
__device__ float g_o2[NTOK * 128];
__device__ float g_y[8 * 128 * 196];
__device__ float g_bnp1[256];
__device__ float g_bnp2[256];

// ------------------------------- K0: zero ----------------------------------
__global__ void k0_zero() {
    int i = blockIdx.x * 256 + threadIdx.x;           // grid 1568x256 = 401408
    if (i < 256) g_stats1[i] = 0.f;
    g_dl[i] = 0.f;                                    // exactly 1568*256 elems
}

// --------------------- K1: mask conv1x1 + BN1 stats ------------------------
// GEMM: t1[b][cs][pix] = sum_ci W[cs][ci] * dec[b][ci][pix] + bias[cs]
// Block: 128 cs x 128 pix, K=256, 256 threads, 8x8 register tile.
__global__ __launch_bounds__(256) void k1_maskconv(
    const float* __restrict__ dec, const float* __restrict__ w,
    const float* __restrict__ bias) {
    __shared__ float As[16][136];   // [k][cs], padded (row base 544B, 16B-mult)
    __shared__ float Bs[16][128];   // [k][pix]
    __shared__ float ssum[128], ssq[128];
    int b = blockIdx.y;
    int pix0 = blockIdx.x * 128;
    int t = threadIdx.x, tx = t & 15, ty = t >> 4;
    float acc[8][8] = {};
    const float* decb = dec + (size_t)b * 256 * S2 + pix0;

    for (int k0 = 0; k0 < 256; k0 += 16) {
#pragma unroll
        for (int l = 0; l < 2; l++) {                 // A: 128cs x 16k
            int j = t + l * 256;
            int cs = j >> 2;
            int kk = (j & 3) * 4;
            float4 wv = *(const float4*)(w + (size_t)cs * 256 + k0 + kk);
            As[kk + 0][cs] = wv.x; As[kk + 1][cs] = wv.y;
            As[kk + 2][cs] = wv.z; As[kk + 3][cs] = wv.w;
        }
#pragma unroll
        for (int l = 0; l < 2; l++) {                 // B: 16k x 128pix
            int j = t + l * 256;
            int kk = j >> 5;
            int p4 = (j & 31) * 4;
            float4 dv = *(const float4*)(decb + (size_t)(k0 + kk) * S2 + p4);
            *(float4*)&Bs[kk][p4] = dv;
        }
        __syncthreads();
#pragma unroll
        for (int k = 0; k < 16; k++) {
            float a[8], bb[8];
#pragma unroll
            for (int i = 0; i < 8; i++) a[i] = As[k][ty * 8 + i];
#pragma unroll
            for (int j = 0; j < 8; j++) bb[j] = Bs[k][tx * 8 + j];
#pragma unroll
            for (int i = 0; i < 8; i++)
#pragma unroll
                for (int j = 0; j < 8; j++)
                    acc[i][j] = fmaf(a[i], bb[j], acc[i][j]);
        }
        __syncthreads();
    }

    if (t < 128) { ssum[t] = 0.f; ssq[t] = 0.f; }
    __syncthreads();
    float* t1b = g_t1 + (size_t)b * 128 * S2 + pix0;
#pragma unroll
    for (int i = 0; i < 8; i++) {
        int cs = ty * 8 + i;
        float bv = bias[cs];
        float ps = 0.f, pq = 0.f;
#pragma unroll
        for (int j = 0; j < 8; j++) {
            float v = acc[i][j] + bv;
            acc[i][j] = v;
            ps += v; pq += v * v;
        }
        atomicAdd(&ssum[cs], ps);
        atomicAdd(&ssq[cs], pq);
        float4 v0 = make_float4(acc[i][0], acc[i][1], acc[i][2], acc[i][3]);
        float4 v1 = make_float4(acc[i][4], acc[i][5], acc[i][6], acc[i][7]);
        *(float4*)(t1b + (size_t)cs * S2 + tx * 8) = v0;
        *(float4*)(t1b + (size_t)cs * S2 + tx * 8 + 4) = v1;
    }
    __syncthreads();
    if (t < 128) {
        atomicAdd(&g_stats1[t], ssum[t]);
        atomicAdd(&g_stats1[128 + t], ssq[t]);
    }
}

// --------------------- K2: patch-embed GEMM (split-K) ----------------------
// dl[n][co] += sum_{k in slice} pe_w[co][k] * patch(n)[k]
// k = ci*256 + ky*16 + kx  (kx fastest, chunks of 16 = one (ci,ky) row)
// Block tile 128(co) x 64(n), K-slice 4096. 256 thr, 8x4 reg tile.
__global__ __launch_bounds__(256) void k2_patch(
    const float* __restrict__ dec, const float* __restrict__ pw) {
    __shared__ float As[16][136];   // [k][co]
    __shared__ float Bs[16][68];    // [k][n]  (row base 272B, 16B-mult)
    int n0 = blockIdx.x * 64;
    int co0 = blockIdx.y * 128;
    int kbase = blockIdx.z * 4096;
    int t = threadIdx.x, tx = t & 15, ty = t >> 4;
    float acc[8][4] = {};

    int nn = t >> 2;                 // 0..63 (this thread's B-load column)
    int kx4 = (t & 3) * 4;
    int n = n0 + nn;
    bool nvalid = n < NTOK;
    int bb = n / 196, r = n % 196, ph = r / 14, pwi = r % 14;
    if (!nvalid) { bb = 0; ph = 0; pwi = 0; }

    for (int kc = 0; kc < 4096; kc += 16) {
        int k0 = kbase + kc;
        int ci = k0 >> 8, ky = (k0 >> 4) & 15;
#pragma unroll
        for (int l = 0; l < 2; l++) {                // A: 128co x 16k
            int j = t + l * 256;
            int co = j >> 2;
            int kk = (j & 3) * 4;
            float4 wv = *(const float4*)(pw + (size_t)(co0 + co) * 65536 + k0 + kk);
            As[kk + 0][co] = wv.x; As[kk + 1][co] = wv.y;
            As[kk + 2][co] = wv.z; As[kk + 3][co] = wv.w;
        }
        {                                            // B: 16kx x 64n
            float4 dv = make_float4(0.f, 0.f, 0.f, 0.f);
            if (nvalid) {
                size_t addr = ((size_t)(bb * 256 + ci) * 224 + 16 * ph + ky) * 224
                              + 16 * pwi + kx4;
                dv = *(const float4*)(dec + addr);
            }
            Bs[kx4 + 0][nn] = dv.x; Bs[kx4 + 1][nn] = dv.y;
            Bs[kx4 + 2][nn] = dv.z; Bs[kx4 + 3][nn] = dv.w;
        }
        __syncthreads();
#pragma unroll
        for (int k = 0; k < 16; k++) {
            float a[8], bv[4];
#pragma unroll
            for (int i = 0; i < 8; i++) a[i] = As[k][ty * 8 + i];
#pragma unroll
            for (int j = 0; j < 4; j++) bv[j] = Bs[k][tx * 4 + j];
#pragma unroll
            for (int i = 0; i < 8; i++)
#pragma unroll
                for (int j = 0; j < 4; j++)
                    acc[i][j] = fmaf(a[i], bv[j], acc[i][j]);
        }
        __syncthreads();
    }
#pragma unroll
    for (int j = 0; j < 4; j++) {
        int n2 = n0 + tx * 4 + j;
        if (n2 < NTOK) {
#pragma unroll
            for (int i = 0; i < 8; i++) {
                int co = co0 + ty * 8 + i;
                atomicAdd(&g_dl[(size_t)n2 * 256 + co], acc[i][j]);
            }
        }
    }
}

// --------------------------- K3: BN1 finalize -------------------------------
__global__ void k3_bn1(const float* __restrict__ g1, const float* __restrict__ b1) {
    int c = threadIdx.x;   // 128
    const float cnt = 401408.f;
    float m = g_stats1[c] / cnt;
    float var = g_stats1[128 + c] / cnt - m * m;
    float a = g1[c] * rsqrtf(var + 1e-5f);
    g_bnp1[c] = a;
    g_bnp1[128 + c] = b1[c] - m * a;
}

// ------------------------------ K4: k, v ------------------------------------
__global__ void k4_kv(const float* __restrict__ trans, const float* __restrict__ wk,
                      const float* __restrict__ wv) {
    __shared__ float rows[8][960];
    int b = blockIdx.y, ng = blockIdx.x, t = threadIdx.x;  // 128 thr
    int nb = ng * 8;
    int nr = 196 - nb; if (nr > 8) nr = 8;
    for (int i = t; i < nr * 960; i += 128) {
        int rr = i / 960, e = i % 960;
        rows[rr][e] = trans[((size_t)(b * 196) + nb + rr) * 960 + e];
    }
    __syncthreads();
    float ak[8] = {}, av[8] = {};
    for (int e = 0; e < 960; e++) {
        float wkv = wk[e * 128 + t], wvv = wv[e * 128 + t];
#pragma unroll
        for (int rr = 0; rr < 8; rr++) {
            ak[rr] = fmaf(rows[rr][e], wkv, ak[rr]);
            av[rr] = fmaf(rows[rr][e], wvv, av[rr]);
        }
    }
    for (int rr = 0; rr < nr; rr++) {
        g_k[((size_t)(b * 196) + nb + rr) * 128 + t] = ak[rr];
        g_v[((size_t)(b * 196) + nb + rr) * 128 + t] = av[rr];
    }
}

// ------------------------------- Kq: q --------------------------------------
__global__ void kq_q(const float* __restrict__ peb, const float* __restrict__ wq) {
    __shared__ float rows[8][256];
    int b = blockIdx.y, ng = blockIdx.x, t = threadIdx.x;  // 128 thr
    int nb = ng * 8;
    int nr = 196 - nb; if (nr > 8) nr = 8;
    for (int i = t; i < nr * 256; i += 128) {
        int rr = i >> 8, d = i & 255;
        rows[rr][d] = g_dl[((size_t)(b * 196) + nb + rr) * 256 + d] + peb[d];
    }
    __syncthreads();
    float acc[8] = {};
    for (int d = 0; d < 256; d++) {
        float wv = wq[d * 128 + t];
#pragma unroll
        for (int rr = 0; rr < 8; rr++) acc[rr] = fmaf(rows[rr][d], wv, acc[rr]);
    }
    for (int rr = 0; rr < nr; rr++)
        g_q[((size_t)(b * 196) + nb + rr) * 128 + t] = acc[rr];
}

// -------------------- K5: sim = q^T k + instance-norm stats ------------------
__global__ __launch_bounds__(256) void k5_sim() {
    __shared__ float Qs[16][128], Ks[16][128];
    __shared__ float red[256];
    int b = blockIdx.x;
    int t = threadIdx.x, tx = t & 15, ty = t >> 4;
    float acc[8][8] = {};
    const float* qb = g_q + (size_t)b * 196 * 128;
    const float* kb = g_k + (size_t)b * 196 * 128;
    for (int n0 = 0; n0 < 196; n0 += 16) {
        int nc = 196 - n0; if (nc > 16) nc = 16;
#pragma unroll
        for (int l = 0; l < 2; l++) {
            int j = t + l * 256;
            int kk = j >> 5, c4 = (j & 31) * 4;
            float4 qv = make_float4(0.f, 0.f, 0.f, 0.f), kv = qv;
            if (kk < nc) {
                qv = *(const float4*)(qb + (size_t)(n0 + kk) * 128 + c4);
                kv = *(const float4*)(kb + (size_t)(n0 + kk) * 128 + c4);
            }
            *(float4*)&Qs[kk][c4] = qv;
            *(float4*)&Ks[kk][c4] = kv;
        }
        __syncthreads();
#pragma unroll
        for (int k = 0; k < 16; k++) {
            float a[8], bb[8];
#pragma unroll
            for (int i = 0; i < 8; i++) a[i] = Qs[k][ty * 8 + i];
#pragma unroll
            for (int j = 0; j < 8; j++) bb[j] = Ks[k][tx * 8 + j];
#pragma unroll
            for (int i = 0; i < 8; i++)
#pragma unroll
                for (int j = 0; j < 8; j++)
                    acc[i][j] = fmaf(a[i], bb[j], acc[i][j]);
        }
        __syncthreads();
    }
    float s = 0.f, q = 0.f;
#pragma unroll
    for (int i = 0; i < 8; i++)
#pragma unroll
        for (int j = 0; j < 8; j++) {
            float v = acc[i][j];
            s += v; q += v * v;
            g_sim[((size_t)b * 128 + ty * 8 + i) * 128 + tx * 8 + j] = v;
        }
    red[t] = s; __syncthreads();
    for (int o = 128; o > 0; o >>= 1) { if (t < o) red[t] += red[t + o]; __syncthreads(); }
    float ssum = red[0]; __syncthreads();
    red[t] = q; __syncthreads();
    for (int o = 128; o > 0; o >>= 1) { if (t < o) red[t] += red[t + o]; __syncthreads(); }
    if (t == 0) {
        float m = ssum / 16384.f;
        float var = red[0] / 16384.f - m * m;
        g_inorm[b * 2] = m;
        g_inorm[b * 2 + 1] = rsqrtf(var + 1e-5f);
    }
}

// ------------------------- K5c: row softmax ---------------------------------
__global__ void k5c_soft() {
    int c = blockIdx.x, b = blockIdx.y, t = threadIdx.x;   // 128 thr
    __shared__ float red[4], red2[4];
    float m = g_inorm[b * 2], rs = g_inorm[b * 2 + 1];
    float v = (g_sim[((size_t)b * 128 + c) * 128 + t] - m) * rs;
    float mx = v;
#pragma unroll
    for (int o = 16; o > 0; o >>= 1) mx = fmaxf(mx, __shfl_xor_sync(0xffffffffu, mx, o));
    if ((t & 31) == 0) red[t >> 5] = mx;
    __syncthreads();
    mx = fmaxf(fmaxf(red[0], red[1]), fmaxf(red[2], red[3]));
    float e = expf(v - mx);
    float s = e;
#pragma unroll
    for (int o = 16; o > 0; o >>= 1) s += __shfl_xor_sync(0xffffffffu, s, o);
    if ((t & 31) == 0) red2[t >> 5] = s;
    __syncthreads();
    s = red2[0] + red2[1] + red2[2] + red2[3];
    g_p[((size_t)b * 128 + c) * 128 + t] = e / s;
}

// ------------------------ K5b: o = P v ; o2 = o wo ---------------------------
__global__ void k5b_o(const float* __restrict__ wo) {
    int n = blockIdx.x, b = blockIdx.y, t = threadIdx.x;   // 128 thr
    __shared__ float vrow[128], orow[128];
    vrow[t] = g_v[((size_t)(b * 196) + n) * 128 + t];
    __syncthreads();
    const float* pb = g_p + (size_t)b * 128 * 128;
    float o = 0.f;
    for (int d = 0; d < 128; d++) o = fmaf(pb[t * 128 + d], vrow[d], o);
    orow[t] = o;
    __syncthreads();
    float o2 = 0.f;
    for (int c = 0; c < 128; c++) o2 = fmaf(orow[c], wo[c * 128 + t], o2);
    g_o2[((size_t)(b * 196) + n) * 128 + t] = o2;
}

// --------------------------- K6: reconstruct conv ----------------------------
__global__ void k6_rec(const float* __restrict__ rw, const float* __restrict__ rb) {
    int n = blockIdx.x, b = blockIdx.y, t = threadIdx.x;   // 128 thr
    __shared__ float xrow[128];
    xrow[t] = g_o2[((size_t)(b * 196) + n) * 128 + t];
    __syncthreads();
    float y = rb[t];
    for (int ci = 0; ci < 128; ci++) y = fmaf(rw[t * 128 + ci], xrow[ci], y);
    g_y[((size_t)(b * 128 + t)) * 196 + n] = y;
}

// ------------------------ K7: BN2 stats + finalize ---------------------------
__global__ void k7_bn2(const float* __restrict__ g2, const float* __restrict__ b2) {
    int co = blockIdx.x, t = threadIdx.x;   // 256 thr
    __shared__ float rs[256], rq[256];
    float s = 0.f, q = 0.f;
    for (int i = t; i < 1568; i += 256) {
        float v = g_y[((size_t)((i / 196) * 128 + co)) * 196 + (i % 196)];
        s += v; q += v * v;
    }
    rs[t] = s; rq[t] = q; __syncthreads();
    for (int o = 128; o > 0; o >>= 1) {
        if (t < o) { rs[t] += rs[t + o]; rq[t] += rq[t + o]; }
        __syncthreads();
    }
    if (t == 0) {
        float m = rs[0] / 1568.f;
        float var = rq[0] / 1568.f - m * m;
        float a = g2[co] * rsqrtf(var + 1e-5f);
        g_bnp2[co] = a;
        g_bnp2[128 + co] = b2[co] - m * a;
    }
}

// ------------------------------ K8: fused epilogue ---------------------------
__global__ void k8_final(float* __restrict__ out) {
    size_t i4 = (size_t)blockIdx.x * 256 + threadIdx.x;   // 50176*256 = 12845056 f4
    int x4 = (int)(i4 % 56);
    size_t r = i4 / 56;
    int y = (int)(r % 224);
    size_t r2 = r / 224;
    int c = (int)(r2 % 128);
    int b = (int)(r2 / 128);
    float4 tv = *(const float4*)(g_t1 + i4 * 4);
    float a1 = g_bnp1[c], b1 = g_bnp1[128 + c];
    float a2 = g_bnp2[c], b2 = g_bnp2[128 + c];
    int n = (y >> 4) * 14 + (x4 >> 2);
    float z = fmaxf(fmaf(a2, g_y[((size_t)(b * 128 + c)) * 196 + n], b2), 0.f);
    float4 o;
    o.x = fmaxf(fmaf(a1, tv.x, b1), 0.f) * z;
    o.y = fmaxf(fmaf(a1, tv.y, b1), 0.f) * z;
    o.z = fmaxf(fmaf(a1, tv.z, b1), 0.f) * z;
    o.w = fmaxf(fmaf(a1, tv.w, b1), 0.f) * z;
    *(float4*)(out + i4 * 4) = o;
}

// ---------------------------------------------------------------------------
extern "C" void kernel_launch(void* const* d_in, const int* in_sizes, int n_in,
                              void* d_out, int out_size) {
    const float* decoder = (const float*)d_in[0];
    const float* trans   = (const float*)d_in[1];
    const float* pe_w    = (const float*)d_in[2];
    const float* pe_b    = (const float*)d_in[3];
    const float* convm_w = (const float*)d_in[4];
    const float* convm_b = (const float*)d_in[5];
    const float* bn1_g   = (const float*)d_in[6];
    const float* bn1_b   = (const float*)d_in[7];
    const float* wq      = (const float*)d_in[8];
    const float* wk      = (const float*)d_in[9];
    const float* wv      = (const float*)d_in[10];
    const float* wo      = (const float*)d_in[11];
    const float* rec_w   = (const float*)d_in[12];
    const float* rec_b   = (const float*)d_in[13];
    const float* bn2_g   = (const float*)d_in[14];
    const float* bn2_b   = (const float*)d_in[15];
    float* out = (float*)d_out;

    k0_zero<<<1568, 256>>>();
    k1_maskconv<<<dim3(392, 8), 256>>>(decoder, convm_w, convm_b);
    k2_patch<<<dim3(25, 2, 16), 256>>>(decoder, pe_w);
    k3_bn1<<<1, 128>>>(bn1_g, bn1_b);
    k4_kv<<<dim3(25, 8), 128>>>(trans, wk, wv);
    kq_q<<<dim3(25, 8), 128>>>(pe_b, wq);
    k5_sim<<<8, 256>>>();
    k5c_soft<<<dim3(128, 8), 128>>>();
    k5b_o<<<dim3(196, 8), 128>>>(wo);
    k6_rec<<<dim3(196, 8), 128>>>(rec_w, rec_b);
    k7_bn2<<<128, 256>>>(bn2_g, bn2_b);
    k8_final<<<50176, 256>>>(out);
}

// round 2
// speedup vs baseline: 1.0552x; 1.0552x over previous
#include <cuda_runtime.h>
#include <cuda_bf16.h>

// ---------------------------------------------------------------------------
// DRA_C: decoder [8,256,224,224], trans [8,196,960] -> out [8,128,224,224]
// Round 2: packed fp32 (fma.rn.f32x2) inner loops for K1/K2 GEMMs.
// ---------------------------------------------------------------------------

#define S2 50176            // 224*224
#define NTOK 1568           // 8*196

// ------------------------- packed f32x2 helpers ----------------------------
__device__ __forceinline__ unsigned long long pack2(float x) {
    unsigned long long r;
    asm("mov.b64 %0, {%1, %1};" : "=l"(r) : "f"(x));
    return r;
}
__device__ __forceinline__ void ffma2(unsigned long long& d,
                                      unsigned long long a,
                                      unsigned long long b) {
    asm("fma.rn.f32x2 %0, %1, %2, %0;" : "+l"(d) : "l"(a), "l"(b));
}
__device__ __forceinline__ float2 unpack2(unsigned long long v) {
    float2 f;
    asm("mov.b64 {%0, %1}, %2;" : "=f"(f.x), "=f"(f.y) : "l"(v));
    return f;
}

// ------------------------- device scratch (static) -------------------------
__device__ float g_t1[8 * 128 * 224 * 224];   // 205 MB
__device__ float g_dl[NTOK * 256];
__device__ float g_stats1[256];
__device__ float g_q[NTOK * 128];
__device__ float g_k[NTOK * 128];
__device__ float g_v[NTOK * 128];
__device__ float g_sim[8 * 128 * 128];
__device__ float g_inorm[16];
__device__ float g_p[8 * 128 * 128];
__device__ float g_o2[NTOK * 128];
__device__ float g_y[8 * 128 * 196];
__device__ float g_bnp1[256];
__device__ float g_bnp2[256];

// ------------------------------- K0: zero ----------------------------------
__global__ void k0_zero() {
    int i = blockIdx.x * 256 + threadIdx.x;           // grid 1568x256 = 401408
    if (i < 256) g_stats1[i] = 0.f;
    g_dl[i] = 0.f;
}

// --------------------- K1: mask conv1x1 + BN1 stats ------------------------
// Block: 128 cs x 128 pix, K=256, 256 threads, 8x8 register tile (f32x2).
__global__ __launch_bounds__(256) void k1_maskconv(
    const float* __restrict__ dec, const float* __restrict__ w,
    const float* __restrict__ bias) {
    __shared__ float As[16][136];   // [k][cs]
    __shared__ float Bs[16][128];   // [k][pix]
    __shared__ float ssum[128], ssq[128];
    int b = blockIdx.y;
    int pix0 = blockIdx.x * 128;
    int t = threadIdx.x, tx = t & 15, ty = t >> 4;
    unsigned long long acc2[4][8];
#pragma unroll
    for (int i = 0; i < 4; i++)
#pragma unroll
        for (int j = 0; j < 8; j++) acc2[i][j] = 0ull;
    const float* decb = dec + (size_t)b * 256 * S2 + pix0;

    for (int k0 = 0; k0 < 256; k0 += 16) {
#pragma unroll
        for (int l = 0; l < 2; l++) {                 // A: 128cs x 16k
            int j = t + l * 256;
            int cs = j >> 2;
            int kk = (j & 3) * 4;
            float4 wv = *(const float4*)(w + (size_t)cs * 256 + k0 + kk);
            As[kk + 0][cs] = wv.x; As[kk + 1][cs] = wv.y;
            As[kk + 2][cs] = wv.z; As[kk + 3][cs] = wv.w;
        }
#pragma unroll
        for (int l = 0; l < 2; l++) {                 // B: 16k x 128pix
            int j = t + l * 256;
            int kk = j >> 5;
            int p4 = (j & 31) * 4;
            float4 dv = *(const float4*)(decb + (size_t)(k0 + kk) * S2 + p4);
            *(float4*)&Bs[kk][p4] = dv;
        }
        __syncthreads();
#pragma unroll
        for (int k = 0; k < 16; k++) {
            unsigned long long a2[4], b2[8];
#pragma unroll
            for (int i = 0; i < 4; i++)
                a2[i] = *(const unsigned long long*)&As[k][ty * 8 + i * 2];
#pragma unroll
            for (int j = 0; j < 8; j++) b2[j] = pack2(Bs[k][tx * 8 + j]);
#pragma unroll
            for (int i = 0; i < 4; i++)
#pragma unroll
                for (int j = 0; j < 8; j++)
                    ffma2(acc2[i][j], a2[i], b2[j]);
        }
        __syncthreads();
    }

    float accf[8][8];
#pragma unroll
    for (int i = 0; i < 4; i++)
#pragma unroll
        for (int j = 0; j < 8; j++) {
            float2 u = unpack2(acc2[i][j]);
            accf[2 * i][j] = u.x;
            accf[2 * i + 1][j] = u.y;
        }

    if (t < 128) { ssum[t] = 0.f; ssq[t] = 0.f; }
    __syncthreads();
    float* t1b = g_t1 + (size_t)b * 128 * S2 + pix0;
#pragma unroll
    for (int i = 0; i < 8; i++) {
        int cs = ty * 8 + i;
        float bv = bias[cs];
        float ps = 0.f, pq = 0.f;
#pragma unroll
        for (int j = 0; j < 8; j++) {
            float v = accf[i][j] + bv;
            accf[i][j] = v;
            ps += v; pq += v * v;
        }
        atomicAdd(&ssum[cs], ps);
        atomicAdd(&ssq[cs], pq);
        float4 v0 = make_float4(accf[i][0], accf[i][1], accf[i][2], accf[i][3]);
        float4 v1 = make_float4(accf[i][4], accf[i][5], accf[i][6], accf[i][7]);
        *(float4*)(t1b + (size_t)cs * S2 + tx * 8) = v0;
        *(float4*)(t1b + (size_t)cs * S2 + tx * 8 + 4) = v1;
    }
    __syncthreads();
    if (t < 128) {
        atomicAdd(&g_stats1[t], ssum[t]);
        atomicAdd(&g_stats1[128 + t], ssq[t]);
    }
}

// --------------------- K2: patch-embed GEMM (split-K) ----------------------
// Block tile 128(co) x 64(n), K-slice 4096. 256 thr, 8x4 reg tile (f32x2).
__global__ __launch_bounds__(256) void k2_patch(
    const float* __restrict__ dec, const float* __restrict__ pw) {
    __shared__ float As[16][136];   // [k][co]
    __shared__ float Bs[16][68];    // [k][n]
    int n0 = blockIdx.x * 64;
    int co0 = blockIdx.y * 128;
    int kbase = blockIdx.z * 4096;
    int t = threadIdx.x, tx = t & 15, ty = t >> 4;
    unsigned long long acc2[4][4];
#pragma unroll
    for (int i = 0; i < 4; i++)
#pragma unroll
        for (int j = 0; j < 4; j++) acc2[i][j] = 0ull;

    int nn = t >> 2;                 // 0..63
    int kx4 = (t & 3) * 4;
    int n = n0 + nn;
    bool nvalid = n < NTOK;
    int bb = n / 196, r = n % 196, ph = r / 14, pwi = r % 14;
    if (!nvalid) { bb = 0; ph = 0; pwi = 0; }

    for (int kc = 0; kc < 4096; kc += 16) {
        int k0 = kbase + kc;
        int ci = k0 >> 8, ky = (k0 >> 4) & 15;
#pragma unroll
        for (int l = 0; l < 2; l++) {                // A: 128co x 16k
            int j = t + l * 256;
            int co = j >> 2;
            int kk = (j & 3) * 4;
            float4 wv = *(const float4*)(pw + (size_t)(co0 + co) * 65536 + k0 + kk);
            As[kk + 0][co] = wv.x; As[kk + 1][co] = wv.y;
            As[kk + 2][co] = wv.z; As[kk + 3][co] = wv.w;
        }
        {                                            // B: 16kx x 64n
            float4 dv = make_float4(0.f, 0.f, 0.f, 0.f);
            if (nvalid) {
                size_t addr = ((size_t)(bb * 256 + ci) * 224 + 16 * ph + ky) * 224
                              + 16 * pwi + kx4;
                dv = *(const float4*)(dec + addr);
            }
            Bs[kx4 + 0][nn] = dv.x; Bs[kx4 + 1][nn] = dv.y;
            Bs[kx4 + 2][nn] = dv.z; Bs[kx4 + 3][nn] = dv.w;
        }
        __syncthreads();
#pragma unroll
        for (int k = 0; k < 16; k++) {
            unsigned long long a2[4], b2[4];
#pragma unroll
            for (int i = 0; i < 4; i++)
                a2[i] = *(const unsigned long long*)&As[k][ty * 8 + i * 2];
#pragma unroll
            for (int j = 0; j < 4; j++) b2[j] = pack2(Bs[k][tx * 4 + j]);
#pragma unroll
            for (int i = 0; i < 4; i++)
#pragma unroll
                for (int j = 0; j < 4; j++)
                    ffma2(acc2[i][j], a2[i], b2[j]);
        }
        __syncthreads();
    }
#pragma unroll
    for (int j = 0; j < 4; j++) {
        int n2 = n0 + tx * 4 + j;
        if (n2 < NTOK) {
#pragma unroll
            for (int i = 0; i < 4; i++) {
                float2 u = unpack2(acc2[i][j]);
                int co = co0 + ty * 8 + 2 * i;
                atomicAdd(&g_dl[(size_t)n2 * 256 + co], u.x);
                atomicAdd(&g_dl[(size_t)n2 * 256 + co + 1], u.y);
            }
        }
    }
}

// --------------------------- K3: BN1 finalize -------------------------------
__global__ void k3_bn1(const float* __restrict__ g1, const float* __restrict__ b1) {
    int c = threadIdx.x;   // 128
    const float cnt = 401408.f;
    float m = g_stats1[c] / cnt;
    float var = g_stats1[128 + c] / cnt - m * m;
    float a = g1[c] * rsqrtf(var + 1e-5f);
    g_bnp1[c] = a;
    g_bnp1[128 + c] = b1[c] - m * a;
}

// ------------------------------ K4: k, v ------------------------------------
__global__ void k4_kv(const float* __restrict__ trans, const float* __restrict__ wk,
                      const float* __restrict__ wv) {
    __shared__ float rows[8][960];
    int b = blockIdx.y, ng = blockIdx.x, t = threadIdx.x;  // 128 thr
    int nb = ng * 8;
    int nr = 196 - nb; if (nr > 8) nr = 8;
    for (int i = t; i < nr * 960; i += 128) {
        int rr = i / 960, e = i % 960;
        rows[rr][e] = trans[((size_t)(b * 196) + nb + rr) * 960 + e];
    }
    __syncthreads();
    float ak[8] = {}, av[8] = {};
    for (int e = 0; e < 960; e++) {
        float wkv = wk[e * 128 + t], wvv = wv[e * 128 + t];
#pragma unroll
        for (int rr = 0; rr < 8; rr++) {
            ak[rr] = fmaf(rows[rr][e], wkv, ak[rr]);
            av[rr] = fmaf(rows[rr][e], wvv, av[rr]);
        }
    }
    for (int rr = 0; rr < nr; rr++) {
        g_k[((size_t)(b * 196) + nb + rr) * 128 + t] = ak[rr];
        g_v[((size_t)(b * 196) + nb + rr) * 128 + t] = av[rr];
    }
}

// ------------------------------- Kq: q --------------------------------------
__global__ void kq_q(const float* __restrict__ peb, const float* __restrict__ wq) {
    __shared__ float rows[8][256];
    int b = blockIdx.y, ng = blockIdx.x, t = threadIdx.x;  // 128 thr
    int nb = ng * 8;
    int nr = 196 - nb; if (nr > 8) nr = 8;
    for (int i = t; i < nr * 256; i += 128) {
        int rr = i >> 8, d = i & 255;
        rows[rr][d] = g_dl[((size_t)(b * 196) + nb + rr) * 256 + d] + peb[d];
    }
    __syncthreads();
    float acc[8] = {};
    for (int d = 0; d < 256; d++) {
        float wv = wq[d * 128 + t];
#pragma unroll
        for (int rr = 0; rr < 8; rr++) acc[rr] = fmaf(rows[rr][d], wv, acc[rr]);
    }
    for (int rr = 0; rr < nr; rr++)
        g_q[((size_t)(b * 196) + nb + rr) * 128 + t] = acc[rr];
}

// -------------------- K5: sim = q^T k + instance-norm stats ------------------
__global__ __launch_bounds__(256) void k5_sim() {
    __shared__ float Qs[16][128], Ks[16][128];
    __shared__ float red[256];
    int b = blockIdx.x;
    int t = threadIdx.x, tx = t & 15, ty = t >> 4;
    float acc[8][8] = {};
    const float* qb = g_q + (size_t)b * 196 * 128;
    const float* kb = g_k + (size_t)b * 196 * 128;
    for (int n0 = 0; n0 < 196; n0 += 16) {
        int nc = 196 - n0; if (nc > 16) nc = 16;
#pragma unroll
        for (int l = 0; l < 2; l++) {
            int j = t + l * 256;
            int kk = j >> 5, c4 = (j & 31) * 4;
            float4 qv = make_float4(0.f, 0.f, 0.f, 0.f), kv = qv;
            if (kk < nc) {
                qv = *(const float4*)(qb + (size_t)(n0 + kk) * 128 + c4);
                kv = *(const float4*)(kb + (size_t)(n0 + kk) * 128 + c4);
            }
            *(float4*)&Qs[kk][c4] = qv;
            *(float4*)&Ks[kk][c4] = kv;
        }
        __syncthreads();
#pragma unroll
        for (int k = 0; k < 16; k++) {
            float a[8], bb[8];
#pragma unroll
            for (int i = 0; i < 8; i++) a[i] = Qs[k][ty * 8 + i];
#pragma unroll
            for (int j = 0; j < 8; j++) bb[j] = Ks[k][tx * 8 + j];
#pragma unroll
            for (int i = 0; i < 8; i++)
#pragma unroll
                for (int j = 0; j < 8; j++)
                    acc[i][j] = fmaf(a[i], bb[j], acc[i][j]);
        }
        __syncthreads();
    }
    float s = 0.f, q = 0.f;
#pragma unroll
    for (int i = 0; i < 8; i++)
#pragma unroll
        for (int j = 0; j < 8; j++) {
            float v = acc[i][j];
            s += v; q += v * v;
            g_sim[((size_t)b * 128 + ty * 8 + i) * 128 + tx * 8 + j] = v;
        }
    red[t] = s; __syncthreads();
    for (int o = 128; o > 0; o >>= 1) { if (t < o) red[t] += red[t + o]; __syncthreads(); }
    float ssum = red[0]; __syncthreads();
    red[t] = q; __syncthreads();
    for (int o = 128; o > 0; o >>= 1) { if (t < o) red[t] += red[t + o]; __syncthreads(); }
    if (t == 0) {
        float m = ssum / 16384.f;
        float var = red[0] / 16384.f - m * m;
        g_inorm[b * 2] = m;
        g_inorm[b * 2 + 1] = rsqrtf(var + 1e-5f);
    }
}

// ------------------------- K5c: row softmax ---------------------------------
__global__ void k5c_soft() {
    int c = blockIdx.x, b = blockIdx.y, t = threadIdx.x;   // 128 thr
    __shared__ float red[4], red2[4];
    float m = g_inorm[b * 2], rs = g_inorm[b * 2 + 1];
    float v = (g_sim[((size_t)b * 128 + c) * 128 + t] - m) * rs;
    float mx = v;
#pragma unroll
    for (int o = 16; o > 0; o >>= 1) mx = fmaxf(mx, __shfl_xor_sync(0xffffffffu, mx, o));
    if ((t & 31) == 0) red[t >> 5] = mx;
    __syncthreads();
    mx = fmaxf(fmaxf(red[0], red[1]), fmaxf(red[2], red[3]));
    float e = expf(v - mx);
    float s = e;
#pragma unroll
    for (int o = 16; o > 0; o >>= 1) s += __shfl_xor_sync(0xffffffffu, s, o);
    if ((t & 31) == 0) red2[t >> 5] = s;
    __syncthreads();
    s = red2[0] + red2[1] + red2[2] + red2[3];
    g_p[((size_t)b * 128 + c) * 128 + t] = e / s;
}

// ------------------------ K5b: o = P v ; o2 = o wo ---------------------------
__global__ void k5b_o(const float* __restrict__ wo) {
    int n = blockIdx.x, b = blockIdx.y, t = threadIdx.x;   // 128 thr
    __shared__ float vrow[128], orow[128];
    vrow[t] = g_v[((size_t)(b * 196) + n) * 128 + t];
    __syncthreads();
    const float* pb = g_p + (size_t)b * 128 * 128;
    float o = 0.f;
    for (int d = 0; d < 128; d++) o = fmaf(pb[t * 128 + d], vrow[d], o);
    orow[t] = o;
    __syncthreads();
    float o2 = 0.f;
    for (int c = 0; c < 128; c++) o2 = fmaf(orow[c], wo[c * 128 + t], o2);
    g_o2[((size_t)(b * 196) + n) * 128 + t] = o2;
}

// --------------------------- K6: reconstruct conv ----------------------------
__global__ void k6_rec(const float* __restrict__ rw, const float* __restrict__ rb) {
    int n = blockIdx.x, b = blockIdx.y, t = threadIdx.x;   // 128 thr
    __shared__ float xrow[128];
    xrow[t] = g_o2[((size_t)(b * 196) + n) * 128 + t];
    __syncthreads();
    float y = rb[t];
    for (int ci = 0; ci < 128; ci++) y = fmaf(rw[t * 128 + ci], xrow[ci], y);
    g_y[((size_t)(b * 128 + t)) * 196 + n] = y;
}

// ------------------------ K7: BN2 stats + finalize ---------------------------
__global__ void k7_bn2(const float* __restrict__ g2, const float* __restrict__ b2) {
    int co = blockIdx.x, t = threadIdx.x;   // 256 thr
    __shared__ float rs[256], rq[256];
    float s = 0.f, q = 0.f;
    for (int i = t; i < 1568; i += 256) {
        float v = g_y[((size_t)((i / 196) * 128 + co)) * 196 + (i % 196)];
        s += v; q += v * v;
    }
    rs[t] = s; rq[t] = q; __syncthreads();
    for (int o = 128; o > 0; o >>= 1) {
        if (t < o) { rs[t] += rs[t + o]; rq[t] += rq[t + o]; }
        __syncthreads();
    }
    if (t == 0) {
        float m = rs[0] / 1568.f;
        float var = rq[0] / 1568.f - m * m;
        float a = g2[co] * rsqrtf(var + 1e-5f);
        g_bnp2[co] = a;
        g_bnp2[128 + co] = b2[co] - m * a;
    }
}

// ------------------------------ K8: fused epilogue ---------------------------
__global__ void k8_final(float* __restrict__ out) {
    size_t i4 = (size_t)blockIdx.x * 256 + threadIdx.x;   // 12845056 float4s
    int x4 = (int)(i4 % 56);
    size_t r = i4 / 56;
    int y = (int)(r % 224);
    size_t r2 = r / 224;
    int c = (int)(r2 % 128);
    int b = (int)(r2 / 128);
    float4 tv = *(const float4*)(g_t1 + i4 * 4);
    float a1 = g_bnp1[c], b1 = g_bnp1[128 + c];
    float a2 = g_bnp2[c], b2 = g_bnp2[128 + c];
    int n = (y >> 4) * 14 + (x4 >> 2);
    float z = fmaxf(fmaf(a2, g_y[((size_t)(b * 128 + c)) * 196 + n], b2), 0.f);
    float4 o;
    o.x = fmaxf(fmaf(a1, tv.x, b1), 0.f) * z;
    o.y = fmaxf(fmaf(a1, tv.y, b1), 0.f) * z;
    o.z = fmaxf(fmaf(a1, tv.z, b1), 0.f) * z;
    o.w = fmaxf(fmaf(a1, tv.w, b1), 0.f) * z;
    *(float4*)(out + i4 * 4) = o;
}

// ---------------------------------------------------------------------------
extern "C" void kernel_launch(void* const* d_in, const int* in_sizes, int n_in,
                              void* d_out, int out_size) {
    const float* decoder = (const float*)d_in[0];
    const float* trans   = (const float*)d_in[1];
    const float* pe_w    = (const float*)d_in[2];
    const float* pe_b    = (const float*)d_in[3];
    const float* convm_w = (const float*)d_in[4];
    const float* convm_b = (const float*)d_in[5];
    const float* bn1_g   = (const float*)d_in[6];
    const float* bn1_b   = (const float*)d_in[7];
    const float* wq      = (const float*)d_in[8];
    const float* wk      = (const float*)d_in[9];
    const float* wv      = (const float*)d_in[10];
    const float* wo      = (const float*)d_in[11];
    const float* rec_w   = (const float*)d_in[12];
    const float* rec_b   = (const float*)d_in[13];
    const float* bn2_g   = (const float*)d_in[14];
    const float* bn2_b   = (const float*)d_in[15];
    float* out = (float*)d_out;

    k0_zero<<<1568, 256>>>();
    k1_maskconv<<<dim3(392, 8), 256>>>(decoder, convm_w, convm_b);
    k2_patch<<<dim3(25, 2, 16), 256>>>(decoder, pe_w);
    k3_bn1<<<1, 128>>>(bn1_g, bn1_b);
    k4_kv<<<dim3(25, 8), 128>>>(trans, wk, wv);
    kq_q<<<dim3(25, 8), 128>>>(pe_b, wq);
    k5_sim<<<8, 256>>>();
    k5c_soft<<<dim3(128, 8), 128>>>();
    k5b_o<<<dim3(196, 8), 128>>>(wo);
    k6_rec<<<dim3(196, 8), 128>>>(rec_w, rec_b);
    k7_bn2<<<128, 256>>>(bn2_g, bn2_b);
    k8_final<<<50176, 256>>>(out);
}

// round 3
// speedup vs baseline: 1.7366x; 1.6457x over previous
#include <cuda_runtime.h>
#include <cuda_bf16.h>
#include <cstdint>

// ---------------------------------------------------------------------------
// DRA_C: decoder [8,256,224,224], trans [8,196,960] -> out [8,128,224,224]
// Round 3: split-bf16 (3-term) tensor-core GEMMs for K1/K2 via mma.sync.
// ---------------------------------------------------------------------------

#define S2 50176            // 224*224
#define NTOK 1568           // 8*196

// ------------------------- device scratch (static) -------------------------
__device__ float g_t1[8 * 128 * 224 * 224];          // 205 MB
__device__ __nv_bfloat16 g_dh[8 * 256 * 224 * 224];  // decoder hi
__device__ __nv_bfloat16 g_dlo[8 * 256 * 224 * 224]; // decoder lo
__device__ __nv_bfloat16 g_pwh[256 * 65536];         // pe_w hi
__device__ __nv_bfloat16 g_pwl[256 * 65536];         // pe_w lo
__device__ __nv_bfloat16 g_wh[128 * 256];            // convm_w hi
__device__ __nv_bfloat16 g_wl[128 * 256];            // convm_w lo
__device__ float g_dl[NTOK * 256];
__device__ float g_stats1[256];
__device__ float g_q[NTOK * 128];
__device__ float g_k[NTOK * 128];
__device__ float g_v[NTOK * 128];
__device__ float g_sim[8 * 128 * 128];
__device__ float g_inorm[16];
__device__ float g_p[8 * 128 * 128];
__device__ float g_o2[NTOK * 128];
__device__ float g_y[8 * 128 * 196];
__device__ float g_bnp1[256];
__device__ float g_bnp2[256];

// ------------------------------ mma helpers --------------------------------
__device__ __forceinline__ uint32_t smem_u32(const void* p) {
    return (uint32_t)__cvta_generic_to_shared(p);
}
__device__ __forceinline__ void ldsm4(uint32_t (&r)[4], uint32_t a) {
    asm volatile("ldmatrix.sync.aligned.m8n8.x4.shared.b16 {%0,%1,%2,%3}, [%4];"
                 : "=r"(r[0]), "=r"(r[1]), "=r"(r[2]), "=r"(r[3]) : "r"(a));
}
__device__ __forceinline__ void ldsm2t(uint32_t (&r)[2], uint32_t a) {
    asm volatile("ldmatrix.sync.aligned.m8n8.x2.trans.shared.b16 {%0,%1}, [%2];"
                 : "=r"(r[0]), "=r"(r[1]) : "r"(a));
}
__device__ __forceinline__ void mma_bf16(float (&c)[4], const uint32_t (&a)[4],
                                         const uint32_t (&b)[2]) {
    asm volatile(
        "mma.sync.aligned.m16n8k16.row.col.f32.bf16.bf16.f32 "
        "{%0,%1,%2,%3}, {%4,%5,%6,%7}, {%8,%9}, {%0,%1,%2,%3};"
        : "+f"(c[0]), "+f"(c[1]), "+f"(c[2]), "+f"(c[3])
        : "r"(a[0]), "r"(a[1]), "r"(a[2]), "r"(a[3]), "r"(b[0]), "r"(b[1]));
}

// ------------------------ Kc: fp32 -> bf16 hi/lo split ----------------------
__global__ void kc_split(const float* __restrict__ x, __nv_bfloat16* __restrict__ hi,
                         __nv_bfloat16* __restrict__ lo) {
    size_t i = ((size_t)blockIdx.x * 256 + threadIdx.x) * 8;
    float4 v0 = *(const float4*)(x + i);
    float4 v1 = *(const float4*)(x + i + 4);
    float v[8] = {v0.x, v0.y, v0.z, v0.w, v1.x, v1.y, v1.z, v1.w};
    union { __nv_bfloat16 h[8]; uint4 u; } H, L;
#pragma unroll
    for (int j = 0; j < 8; j++) {
        __nv_bfloat16 h = __float2bfloat16(v[j]);
        H.h[j] = h;
        L.h[j] = __float2bfloat16(v[j] - __bfloat162float(h));
    }
    *(uint4*)(hi + i) = H.u;
    *(uint4*)(lo + i) = L.u;
}

// ------------------------------- K0: zero ----------------------------------
__global__ void k0_zero() {
    int i = blockIdx.x * 256 + threadIdx.x;
    if (i < 256) g_stats1[i] = 0.f;
    g_dl[i] = 0.f;
}

// --------------------- K1: mask conv1x1 + BN1 stats (mma) -------------------
// C[cs=128][pix=128 per block], K=256, BK=32. 8 warps: 2x4, warp tile 64x32.
__global__ __launch_bounds__(256) void k1_maskconv(const float* __restrict__ bias) {
    __shared__ __nv_bfloat16 Ah[128][40], Al[128][40];
    __shared__ __nv_bfloat16 Bh[32][136], Bl[32][136];
    __shared__ float ssum[128], ssq[128];
    int b = blockIdx.y;
    int pix0 = blockIdx.x * 128;
    int t = threadIdx.x;
    int wid = t >> 5, lane = t & 31;
    int wm = wid >> 2, wn = wid & 3;
    int gid = lane >> 2, tig = lane & 3;
    float c[4][4][4];
#pragma unroll
    for (int i = 0; i < 4; i++)
#pragma unroll
        for (int j = 0; j < 4; j++)
#pragma unroll
            for (int r = 0; r < 4; r++) c[i][j][r] = 0.f;

    const __nv_bfloat16* dhB = g_dh + (size_t)b * 256 * S2 + pix0;
    const __nv_bfloat16* dlB = g_dlo + (size_t)b * 256 * S2 + pix0;

    int arow[2], ac[2], brow[2], bc[2];
#pragma unroll
    for (int l = 0; l < 2; l++) {
        int idx = t + l * 256;
        arow[l] = idx >> 2; ac[l] = (idx & 3) * 8;
        brow[l] = idx >> 4; bc[l] = (idx & 15) * 8;
    }
    uint4 pah[2], pal[2], pbh[2], pbl[2];
#pragma unroll
    for (int l = 0; l < 2; l++) {
        pah[l] = *(const uint4*)(g_wh + arow[l] * 256 + ac[l]);
        pal[l] = *(const uint4*)(g_wl + arow[l] * 256 + ac[l]);
        pbh[l] = *(const uint4*)(dhB + (size_t)brow[l] * S2 + bc[l]);
        pbl[l] = *(const uint4*)(dlB + (size_t)brow[l] * S2 + bc[l]);
    }

    for (int k0 = 0; k0 < 256; k0 += 32) {
#pragma unroll
        for (int l = 0; l < 2; l++) {
            *(uint4*)&Ah[arow[l]][ac[l]] = pah[l];
            *(uint4*)&Al[arow[l]][ac[l]] = pal[l];
            *(uint4*)&Bh[brow[l]][bc[l]] = pbh[l];
            *(uint4*)&Bl[brow[l]][bc[l]] = pbl[l];
        }
        __syncthreads();
        int kn = k0 + 32;
        if (kn < 256) {
#pragma unroll
            for (int l = 0; l < 2; l++) {
                pah[l] = *(const uint4*)(g_wh + arow[l] * 256 + kn + ac[l]);
                pal[l] = *(const uint4*)(g_wl + arow[l] * 256 + kn + ac[l]);
                pbh[l] = *(const uint4*)(dhB + (size_t)(kn + brow[l]) * S2 + bc[l]);
                pbl[l] = *(const uint4*)(dlB + (size_t)(kn + brow[l]) * S2 + bc[l]);
            }
        }
#pragma unroll
        for (int ks = 0; ks < 2; ks++) {
            uint32_t ah[4][4], al2[4][4], bh[4][2], bl2[4][2];
#pragma unroll
            for (int mt = 0; mt < 4; mt++) {
                int r = wm * 64 + mt * 16 + (lane & 15);
                int kc = ks * 16 + (lane >> 4) * 8;
                ldsm4(ah[mt], smem_u32(&Ah[r][kc]));
                ldsm4(al2[mt], smem_u32(&Al[r][kc]));
            }
#pragma unroll
            for (int nt = 0; nt < 4; nt++) {
                int kr = ks * 16 + (lane & 15);
                int col = wn * 32 + nt * 8;
                ldsm2t(bh[nt], smem_u32(&Bh[kr][col]));
                ldsm2t(bl2[nt], smem_u32(&Bl[kr][col]));
            }
#pragma unroll
            for (int mt = 0; mt < 4; mt++)
#pragma unroll
                for (int nt = 0; nt < 4; nt++) {
                    mma_bf16(c[mt][nt], ah[mt], bh[nt]);
                    mma_bf16(c[mt][nt], ah[mt], bl2[nt]);
                    mma_bf16(c[mt][nt], al2[mt], bh[nt]);
                }
        }
        __syncthreads();
    }

    if (t < 128) { ssum[t] = 0.f; ssq[t] = 0.f; }
    __syncthreads();
    float* t1b = g_t1 + (size_t)b * 128 * S2 + pix0;
#pragma unroll
    for (int mt = 0; mt < 4; mt++)
#pragma unroll
        for (int h = 0; h < 2; h++) {
            int cs = wm * 64 + mt * 16 + gid + h * 8;
            float bv = bias[cs];
            float ps = 0.f, pq = 0.f;
#pragma unroll
            for (int nt = 0; nt < 4; nt++) {
                float v0 = c[mt][nt][h * 2 + 0] + bv;
                float v1 = c[mt][nt][h * 2 + 1] + bv;
                ps += v0 + v1; pq += v0 * v0 + v1 * v1;
                int col = wn * 32 + nt * 8 + 2 * tig;
                *(float2*)(t1b + (size_t)cs * S2 + col) = make_float2(v0, v1);
            }
            atomicAdd(&ssum[cs], ps);
            atomicAdd(&ssq[cs], pq);
        }
    __syncthreads();
    if (t < 128) {
        atomicAdd(&g_stats1[t], ssum[t]);
        atomicAdd(&g_stats1[128 + t], ssq[t]);
    }
}

// ------------------- K2: patch-embed GEMM (mma, split-K) --------------------
// C[token 128][co 128] per block, K-slice 4096, BK=32. A=patches, B=pe_w.
__global__ __launch_bounds__(256) void k2_patch() {
    __shared__ __nv_bfloat16 Pah[128][40], Pal[128][40];
    __shared__ __nv_bfloat16 Wbh[128][40], Wbl[128][40];
    int n0 = blockIdx.x * 128;
    int co0 = blockIdx.y * 128;
    int kbase = blockIdx.z * 4096;
    int t = threadIdx.x;
    int wid = t >> 5, lane = t & 31;
    int wm = wid >> 2, wn = wid & 3;
    int gid = lane >> 2, tig = lane & 3;
    float c[4][4][4];
#pragma unroll
    for (int i = 0; i < 4; i++)
#pragma unroll
        for (int j = 0; j < 4; j++)
#pragma unroll
            for (int r = 0; r < 4; r++) c[i][j][r] = 0.f;

    // per-thread A-load coords (2 loads per buffer)
    size_t pbase[2]; int asm_r[2], asm_c[2]; bool avalid[2];
    int wrow[2], wc[2];
#pragma unroll
    for (int l = 0; l < 2; l++) {
        int idx = t + l * 256;
        int nl = idx >> 2, part = idx & 3;
        int kyo = part >> 1, kx8 = (part & 1) * 8;
        int n = n0 + nl;
        avalid[l] = n < NTOK;
        int bb = avalid[l] ? n / 196 : 0;
        int rr = avalid[l] ? n % 196 : 0;
        int ph = rr / 14, pwv = rr % 14;
        pbase[l] = (size_t)bb * 256 * S2 + (size_t)(16 * ph + kyo) * 224 + 16 * pwv + kx8;
        asm_r[l] = nl; asm_c[l] = kyo * 16 + kx8;
        wrow[l] = idx >> 2; wc[l] = (idx & 3) * 8;
    }

    uint4 pah[2], pal[2], pbh[2], pbl[2];
    {
        int k0 = kbase;
        int ci = k0 >> 8, ky = (k0 >> 4) & 15;
#pragma unroll
        for (int l = 0; l < 2; l++) {
            uint4 z = make_uint4(0, 0, 0, 0);
            pah[l] = z; pal[l] = z;
            if (avalid[l]) {
                size_t e = pbase[l] + (size_t)ci * S2 + ky * 224;
                pah[l] = *(const uint4*)(g_dh + e);
                pal[l] = *(const uint4*)(g_dlo + e);
            }
            pbh[l] = *(const uint4*)(g_pwh + (size_t)(co0 + wrow[l]) * 65536 + k0 + wc[l]);
            pbl[l] = *(const uint4*)(g_pwl + (size_t)(co0 + wrow[l]) * 65536 + k0 + wc[l]);
        }
    }

    for (int kc = 0; kc < 4096; kc += 32) {
#pragma unroll
        for (int l = 0; l < 2; l++) {
            *(uint4*)&Pah[asm_r[l]][asm_c[l]] = pah[l];
            *(uint4*)&Pal[asm_r[l]][asm_c[l]] = pal[l];
            *(uint4*)&Wbh[wrow[l]][wc[l]] = pbh[l];
            *(uint4*)&Wbl[wrow[l]][wc[l]] = pbl[l];
        }
        __syncthreads();
        int kcn = kc + 32;
        if (kcn < 4096) {
            int k0 = kbase + kcn;
            int ci = k0 >> 8, ky = (k0 >> 4) & 15;
#pragma unroll
            for (int l = 0; l < 2; l++) {
                if (avalid[l]) {
                    size_t e = pbase[l] + (size_t)ci * S2 + ky * 224;
                    pah[l] = *(const uint4*)(g_dh + e);
                    pal[l] = *(const uint4*)(g_dlo + e);
                }
                pbh[l] = *(const uint4*)(g_pwh + (size_t)(co0 + wrow[l]) * 65536 + k0 + wc[l]);
                pbl[l] = *(const uint4*)(g_pwl + (size_t)(co0 + wrow[l]) * 65536 + k0 + wc[l]);
            }
        }
#pragma unroll
        for (int ks = 0; ks < 2; ks++) {
            int kk = ks * 16;
            uint32_t ah[4][4], al2[4][4], bh[4][2], bl2[4][2];
#pragma unroll
            for (int mt = 0; mt < 4; mt++) {
                int r = wm * 64 + mt * 16 + gid;
                ah[mt][0] = *(const uint32_t*)&Pah[r][kk + 2 * tig];
                ah[mt][1] = *(const uint32_t*)&Pah[r + 8][kk + 2 * tig];
                ah[mt][2] = *(const uint32_t*)&Pah[r][kk + 2 * tig + 8];
                ah[mt][3] = *(const uint32_t*)&Pah[r + 8][kk + 2 * tig + 8];
                al2[mt][0] = *(const uint32_t*)&Pal[r][kk + 2 * tig];
                al2[mt][1] = *(const uint32_t*)&Pal[r + 8][kk + 2 * tig];
                al2[mt][2] = *(const uint32_t*)&Pal[r][kk + 2 * tig + 8];
                al2[mt][3] = *(const uint32_t*)&Pal[r + 8][kk + 2 * tig + 8];
            }
#pragma unroll
            for (int nt = 0; nt < 4; nt++) {
                int cr = wn * 32 + nt * 8 + gid;
                bh[nt][0] = *(const uint32_t*)&Wbh[cr][kk + 2 * tig];
                bh[nt][1] = *(const uint32_t*)&Wbh[cr][kk + 2 * tig + 8];
                bl2[nt][0] = *(const uint32_t*)&Wbl[cr][kk + 2 * tig];
                bl2[nt][1] = *(const uint32_t*)&Wbl[cr][kk + 2 * tig + 8];
            }
#pragma unroll
            for (int mt = 0; mt < 4; mt++)
#pragma unroll
                for (int nt = 0; nt < 4; nt++) {
                    mma_bf16(c[mt][nt], ah[mt], bh[nt]);
                    mma_bf16(c[mt][nt], ah[mt], bl2[nt]);
                    mma_bf16(c[mt][nt], al2[mt], bh[nt]);
                }
        }
        __syncthreads();
    }
#pragma unroll
    for (int mt = 0; mt < 4; mt++)
#pragma unroll
        for (int h = 0; h < 2; h++) {
            int tok = n0 + wm * 64 + mt * 16 + gid + h * 8;
            if (tok < NTOK) {
#pragma unroll
                for (int nt = 0; nt < 4; nt++) {
                    int co = co0 + wn * 32 + nt * 8 + 2 * tig;
                    atomicAdd(&g_dl[(size_t)tok * 256 + co], c[mt][nt][h * 2]);
                    atomicAdd(&g_dl[(size_t)tok * 256 + co + 1], c[mt][nt][h * 2 + 1]);
                }
            }
        }
}

// --------------------------- K3: BN1 finalize -------------------------------
__global__ void k3_bn1(const float* __restrict__ g1, const float* __restrict__ b1) {
    int c = threadIdx.x;
    const float cnt = 401408.f;
    float m = g_stats1[c] / cnt;
    float var = g_stats1[128 + c] / cnt - m * m;
    float a = g1[c] * rsqrtf(var + 1e-5f);
    g_bnp1[c] = a;
    g_bnp1[128 + c] = b1[c] - m * a;
}

// ------------------------------ K4: k, v ------------------------------------
__global__ void k4_kv(const float* __restrict__ trans, const float* __restrict__ wk,
                      const float* __restrict__ wv) {
    __shared__ float rows[8][960];
    int b = blockIdx.y, ng = blockIdx.x, t = threadIdx.x;
    int nb = ng * 8;
    int nr = 196 - nb; if (nr > 8) nr = 8;
    for (int i = t; i < nr * 960; i += 128) {
        int rr = i / 960, e = i % 960;
        rows[rr][e] = trans[((size_t)(b * 196) + nb + rr) * 960 + e];
    }
    __syncthreads();
    float ak[8] = {}, av[8] = {};
    for (int e = 0; e < 960; e++) {
        float wkv = wk[e * 128 + t], wvv = wv[e * 128 + t];
#pragma unroll
        for (int rr = 0; rr < 8; rr++) {
            ak[rr] = fmaf(rows[rr][e], wkv, ak[rr]);
            av[rr] = fmaf(rows[rr][e], wvv, av[rr]);
        }
    }
    for (int rr = 0; rr < nr; rr++) {
        g_k[((size_t)(b * 196) + nb + rr) * 128 + t] = ak[rr];
        g_v[((size_t)(b * 196) + nb + rr) * 128 + t] = av[rr];
    }
}

// ------------------------------- Kq: q --------------------------------------
__global__ void kq_q(const float* __restrict__ peb, const float* __restrict__ wq) {
    __shared__ float rows[8][256];
    int b = blockIdx.y, ng = blockIdx.x, t = threadIdx.x;
    int nb = ng * 8;
    int nr = 196 - nb; if (nr > 8) nr = 8;
    for (int i = t; i < nr * 256; i += 128) {
        int rr = i >> 8, d = i & 255;
        rows[rr][d] = g_dl[((size_t)(b * 196) + nb + rr) * 256 + d] + peb[d];
    }
    __syncthreads();
    float acc[8] = {};
    for (int d = 0; d < 256; d++) {
        float wv = wq[d * 128 + t];
#pragma unroll
        for (int rr = 0; rr < 8; rr++) acc[rr] = fmaf(rows[rr][d], wv, acc[rr]);
    }
    for (int rr = 0; rr < nr; rr++)
        g_q[((size_t)(b * 196) + nb + rr) * 128 + t] = acc[rr];
}

// -------------------- K5: sim = q^T k + instance-norm stats ------------------
__global__ __launch_bounds__(256) void k5_sim() {
    __shared__ float Qs[16][128], Ks[16][128];
    __shared__ float red[256];
    int b = blockIdx.x;
    int t = threadIdx.x, tx = t & 15, ty = t >> 4;
    float acc[8][8] = {};
    const float* qb = g_q + (size_t)b * 196 * 128;
    const float* kb = g_k + (size_t)b * 196 * 128;
    for (int n0 = 0; n0 < 196; n0 += 16) {
        int nc = 196 - n0; if (nc > 16) nc = 16;
#pragma unroll
        for (int l = 0; l < 2; l++) {
            int j = t + l * 256;
            int kk = j >> 5, c4 = (j & 31) * 4;
            float4 qv = make_float4(0.f, 0.f, 0.f, 0.f), kv = qv;
            if (kk < nc) {
                qv = *(const float4*)(qb + (size_t)(n0 + kk) * 128 + c4);
                kv = *(const float4*)(kb + (size_t)(n0 + kk) * 128 + c4);
            }
            *(float4*)&Qs[kk][c4] = qv;
            *(float4*)&Ks[kk][c4] = kv;
        }
        __syncthreads();
#pragma unroll
        for (int k = 0; k < 16; k++) {
            float a[8], bb[8];
#pragma unroll
            for (int i = 0; i < 8; i++) a[i] = Qs[k][ty * 8 + i];
#pragma unroll
            for (int j = 0; j < 8; j++) bb[j] = Ks[k][tx * 8 + j];
#pragma unroll
            for (int i = 0; i < 8; i++)
#pragma unroll
                for (int j = 0; j < 8; j++)
                    acc[i][j] = fmaf(a[i], bb[j], acc[i][j]);
        }
        __syncthreads();
    }
    float s = 0.f, q = 0.f;
#pragma unroll
    for (int i = 0; i < 8; i++)
#pragma unroll
        for (int j = 0; j < 8; j++) {
            float v = acc[i][j];
            s += v; q += v * v;
            g_sim[((size_t)b * 128 + ty * 8 + i) * 128 + tx * 8 + j] = v;
        }
    red[t] = s; __syncthreads();
    for (int o = 128; o > 0; o >>= 1) { if (t < o) red[t] += red[t + o]; __syncthreads(); }
    float ssum = red[0]; __syncthreads();
    red[t] = q; __syncthreads();
    for (int o = 128; o > 0; o >>= 1) { if (t < o) red[t] += red[t + o]; __syncthreads(); }
    if (t == 0) {
        float m = ssum / 16384.f;
        float var = red[0] / 16384.f - m * m;
        g_inorm[b * 2] = m;
        g_inorm[b * 2 + 1] = rsqrtf(var + 1e-5f);
    }
}

// ------------------------- K5c: row softmax ---------------------------------
__global__ void k5c_soft() {
    int c = blockIdx.x, b = blockIdx.y, t = threadIdx.x;
    __shared__ float red[4], red2[4];
    float m = g_inorm[b * 2], rs = g_inorm[b * 2 + 1];
    float v = (g_sim[((size_t)b * 128 + c) * 128 + t] - m) * rs;
    float mx = v;
#pragma unroll
    for (int o = 16; o > 0; o >>= 1) mx = fmaxf(mx, __shfl_xor_sync(0xffffffffu, mx, o));
    if ((t & 31) == 0) red[t >> 5] = mx;
    __syncthreads();
    mx = fmaxf(fmaxf(red[0], red[1]), fmaxf(red[2], red[3]));
    float e = expf(v - mx);
    float s = e;
#pragma unroll
    for (int o = 16; o > 0; o >>= 1) s += __shfl_xor_sync(0xffffffffu, s, o);
    if ((t & 31) == 0) red2[t >> 5] = s;
    __syncthreads();
    s = red2[0] + red2[1] + red2[2] + red2[3];
    g_p[((size_t)b * 128 + c) * 128 + t] = e / s;
}

// ------------------------ K5b: o = P v ; o2 = o wo ---------------------------
__global__ void k5b_o(const float* __restrict__ wo) {
    int n = blockIdx.x, b = blockIdx.y, t = threadIdx.x;
    __shared__ float vrow[128], orow[128];
    vrow[t] = g_v[((size_t)(b * 196) + n) * 128 + t];
    __syncthreads();
    const float* pb = g_p + (size_t)b * 128 * 128;
    float o = 0.f;
    for (int d = 0; d < 128; d++) o = fmaf(pb[t * 128 + d], vrow[d], o);
    orow[t] = o;
    __syncthreads();
    float o2 = 0.f;
    for (int c = 0; c < 128; c++) o2 = fmaf(orow[c], wo[c * 128 + t], o2);
    g_o2[((size_t)(b * 196) + n) * 128 + t] = o2;
}

// --------------------------- K6: reconstruct conv ----------------------------
__global__ void k6_rec(const float* __restrict__ rw, const float* __restrict__ rb) {
    int n = blockIdx.x, b = blockIdx.y, t = threadIdx.x;
    __shared__ float xrow[128];
    xrow[t] = g_o2[((size_t)(b * 196) + n) * 128 + t];
    __syncthreads();
    float y = rb[t];
    for (int ci = 0; ci < 128; ci++) y = fmaf(rw[t * 128 + ci], xrow[ci], y);
    g_y[((size_t)(b * 128 + t)) * 196 + n] = y;
}

// ------------------------ K7: BN2 stats + finalize ---------------------------
__global__ void k7_bn2(const float* __restrict__ g2, const float* __restrict__ b2) {
    int co = blockIdx.x, t = threadIdx.x;
    __shared__ float rs[256], rq[256];
    float s = 0.f, q = 0.f;
    for (int i = t; i < 1568; i += 256) {
        float v = g_y[((size_t)((i / 196) * 128 + co)) * 196 + (i % 196)];
        s += v; q += v * v;
    }
    rs[t] = s; rq[t] = q; __syncthreads();
    for (int o = 128; o > 0; o >>= 1) {
        if (t < o) { rs[t] += rs[t + o]; rq[t] += rq[t + o]; }
        __syncthreads();
    }
    if (t == 0) {
        float m = rs[0] / 1568.f;
        float var = rq[0] / 1568.f - m * m;
        float a = g2[co] * rsqrtf(var + 1e-5f);
        g_bnp2[co] = a;
        g_bnp2[128 + co] = b2[co] - m * a;
    }
}

// ------------------------------ K8: fused epilogue ---------------------------
__global__ void k8_final(float* __restrict__ out) {
    size_t i4 = (size_t)blockIdx.x * 256 + threadIdx.x;
    int x4 = (int)(i4 % 56);
    size_t r = i4 / 56;
    int y = (int)(r % 224);
    size_t r2 = r / 224;
    int c = (int)(r2 % 128);
    int b = (int)(r2 / 128);
    float4 tv = *(const float4*)(g_t1 + i4 * 4);
    float a1 = g_bnp1[c], b1 = g_bnp1[128 + c];
    float a2 = g_bnp2[c], b2 = g_bnp2[128 + c];
    int n = (y >> 4) * 14 + (x4 >> 2);
    float z = fmaxf(fmaf(a2, g_y[((size_t)(b * 128 + c)) * 196 + n], b2), 0.f);
    float4 o;
    o.x = fmaxf(fmaf(a1, tv.x, b1), 0.f) * z;
    o.y = fmaxf(fmaf(a1, tv.y, b1), 0.f) * z;
    o.z = fmaxf(fmaf(a1, tv.z, b1), 0.f) * z;
    o.w = fmaxf(fmaf(a1, tv.w, b1), 0.f) * z;
    *(float4*)(out + i4 * 4) = o;
}

// ---------------------------------------------------------------------------
extern "C" void kernel_launch(void* const* d_in, const int* in_sizes, int n_in,
                              void* d_out, int out_size) {
    const float* decoder = (const float*)d_in[0];
    const float* trans   = (const float*)d_in[1];
    const float* pe_w    = (const float*)d_in[2];
    const float* pe_b    = (const float*)d_in[3];
    const float* convm_w = (const float*)d_in[4];
    const float* convm_b = (const float*)d_in[5];
    const float* bn1_g   = (const float*)d_in[6];
    const float* bn1_b   = (const float*)d_in[7];
    const float* wq      = (const float*)d_in[8];
    const float* wk      = (const float*)d_in[9];
    const float* wv      = (const float*)d_in[10];
    const float* wo      = (const float*)d_in[11];
    const float* rec_w   = (const float*)d_in[12];
    const float* rec_b   = (const float*)d_in[13];
    const float* bn2_g   = (const float*)d_in[14];
    const float* bn2_b   = (const float*)d_in[15];
    float* out = (float*)d_out;

    __nv_bfloat16 *p_dh, *p_dlo, *p_pwh, *p_pwl, *p_wh, *p_wl;
    cudaGetSymbolAddress((void**)&p_dh, g_dh);
    cudaGetSymbolAddress((void**)&p_dlo, g_dlo);
    cudaGetSymbolAddress((void**)&p_pwh, g_pwh);
    cudaGetSymbolAddress((void**)&p_pwl, g_pwl);
    cudaGetSymbolAddress((void**)&p_wh, g_wh);
    cudaGetSymbolAddress((void**)&p_wl, g_wl);

    kc_split<<<50176, 256>>>(decoder, p_dh, p_dlo);   // 102,760,448 elems
    kc_split<<<8192, 256>>>(pe_w, p_pwh, p_pwl);      // 16,777,216 elems
    kc_split<<<16, 256>>>(convm_w, p_wh, p_wl);       // 32,768 elems
    k0_zero<<<1568, 256>>>();
    k1_maskconv<<<dim3(392, 8), 256>>>(convm_b);
    k2_patch<<<dim3(13, 2, 16), 256>>>();
    k3_bn1<<<1, 128>>>(bn1_g, bn1_b);
    k4_kv<<<dim3(25, 8), 128>>>(trans, wk, wv);
    kq_q<<<dim3(25, 8), 128>>>(pe_b, wq);
    k5_sim<<<8, 256>>>();
    k5c_soft<<<dim3(128, 8), 128>>>();
    k5b_o<<<dim3(196, 8), 128>>>(wo);
    k6_rec<<<dim3(196, 8), 128>>>(rec_w, rec_b);
    k7_bn2<<<128, 256>>>(bn2_g, bn2_b);
    k8_final<<<50176, 256>>>(out);
}

// round 4
// speedup vs baseline: 2.1372x; 1.2307x over previous
#include <cuda_runtime.h>
#include <cuda_bf16.h>
#include <cstdint>

// ---------------------------------------------------------------------------
// DRA_C: decoder [8,256,224,224], trans [8,196,960] -> out [8,128,224,224]
// Round 4: fold wq into patch-embed weights (W2 = pe_w^T wq), inline fp32->
// bf16 hi/lo split inside the GEMMs (no decoder pre-split pass).
// ---------------------------------------------------------------------------

#define S2 50176            // 224*224
#define NTOK 1568           // 8*196

// ------------------------- device scratch (static) -------------------------
__device__ float g_t1[8 * 128 * 224 * 224];          // 205 MB
__device__ __nv_bfloat16 g_w2h[128 * 65536];         // folded patch weight hi
__device__ __nv_bfloat16 g_w2l[128 * 65536];         // folded patch weight lo
__device__ __nv_bfloat16 g_wh[128 * 256];            // convm_w hi
__device__ __nv_bfloat16 g_wl[128 * 256];            // convm_w lo
__device__ float g_stats1[256];
__device__ float g_qbias[128];
__device__ float g_q[NTOK * 128];
__device__ float g_k[NTOK * 128];
__device__ float g_v[NTOK * 128];
__device__ float g_sim[8 * 128 * 128];
__device__ float g_inorm[16];
__device__ float g_p[8 * 128 * 128];
__device__ float g_o2[NTOK * 128];
__device__ float g_y[8 * 128 * 196];
__device__ float g_bnp1[256];
__device__ float g_bnp2[256];

// ------------------------------ helpers ------------------------------------
__device__ __forceinline__ uint32_t smem_u32(const void* p) {
    return (uint32_t)__cvta_generic_to_shared(p);
}
__device__ __forceinline__ void ldsm4(uint32_t (&r)[4], uint32_t a) {
    asm volatile("ldmatrix.sync.aligned.m8n8.x4.shared.b16 {%0,%1,%2,%3}, [%4];"
                 : "=r"(r[0]), "=r"(r[1]), "=r"(r[2]), "=r"(r[3]) : "r"(a));
}
__device__ __forceinline__ void ldsm2t(uint32_t (&r)[2], uint32_t a) {
    asm volatile("ldmatrix.sync.aligned.m8n8.x2.trans.shared.b16 {%0,%1}, [%2];"
                 : "=r"(r[0]), "=r"(r[1]) : "r"(a));
}
__device__ __forceinline__ void mma_bf16(float (&c)[4], const uint32_t (&a)[4],
                                         const uint32_t (&b)[2]) {
    asm volatile(
        "mma.sync.aligned.m16n8k16.row.col.f32.bf16.bf16.f32 "
        "{%0,%1,%2,%3}, {%4,%5,%6,%7}, {%8,%9}, {%0,%1,%2,%3};"
        : "+f"(c[0]), "+f"(c[1]), "+f"(c[2]), "+f"(c[3])
        : "r"(a[0]), "r"(a[1]), "r"(a[2]), "r"(a[3]), "r"(b[0]), "r"(b[1]));
}
union BfPack { __nv_bfloat16 h[8]; uint4 u; };
__device__ __forceinline__ void split8(const float4& v0, const float4& v1,
                                       uint4& hi, uint4& lo) {
    float f[8] = {v0.x, v0.y, v0.z, v0.w, v1.x, v1.y, v1.z, v1.w};
    BfPack H, L;
#pragma unroll
    for (int j = 0; j < 8; j++) {
        __nv_bfloat16 h = __float2bfloat16(f[j]);
        H.h[j] = h;
        L.h[j] = __float2bfloat16(f[j] - __bfloat162float(h));
    }
    hi = H.u; lo = L.u;
}

// ------------------------ Kc: fp32 -> bf16 hi/lo split (small) --------------
__global__ void kc_split(const float* __restrict__ x, __nv_bfloat16* __restrict__ hi,
                         __nv_bfloat16* __restrict__ lo) {
    size_t i = ((size_t)blockIdx.x * 256 + threadIdx.x) * 8;
    float4 v0 = *(const float4*)(x + i);
    float4 v1 = *(const float4*)(x + i + 4);
    uint4 H, L;
    split8(v0, v1, H, L);
    *(uint4*)(hi + i) = H;
    *(uint4*)(lo + i) = L;
}

// ------------------------------- K0: zero stats -----------------------------
__global__ void k0_zero() { g_stats1[threadIdx.x] = 0.f; }

// -------------- Kw: W2[c][k] = sum_d wq[d][c] * pe_w[d][k] ------------------
// Block: 128 c x 128 k, K=256 (d). Output written as bf16 hi/lo.
__global__ __launch_bounds__(256) void kw_w2(const float* __restrict__ pw,
                                             const float* __restrict__ wq) {
    __shared__ __nv_bfloat16 Ah[128][40], Al[128][40];   // [c][d32]
    __shared__ __nv_bfloat16 Bh[32][136], Bl[32][136];   // [d][k128]
    int k0g = blockIdx.x * 128;
    int t = threadIdx.x, wid = t >> 5, lane = t & 31;
    int wm = wid >> 2, wn = wid & 3;
    int gid = lane >> 2, tig = lane & 3;
    float c[4][4][4];
#pragma unroll
    for (int i = 0; i < 4; i++)
#pragma unroll
        for (int j = 0; j < 4; j++)
#pragma unroll
            for (int r = 0; r < 4; r++) c[i][j][r] = 0.f;

    for (int d0 = 0; d0 < 256; d0 += 32) {
        // A: transpose wq[d][c] -> Ah[c][d]
#pragma unroll
        for (int l = 0; l < 4; l++) {
            int fi = t + l * 256;
            int dd = fi >> 5, c4 = (fi & 31) * 4;
            float4 v = *(const float4*)(wq + (size_t)(d0 + dd) * 128 + c4);
            float f[4] = {v.x, v.y, v.z, v.w};
#pragma unroll
            for (int j = 0; j < 4; j++) {
                __nv_bfloat16 h = __float2bfloat16(f[j]);
                Ah[c4 + j][dd] = h;
                Al[c4 + j][dd] = __float2bfloat16(f[j] - __bfloat162float(h));
            }
        }
        // B: pe_w rows (fp32 -> hi/lo)
#pragma unroll
        for (int l = 0; l < 2; l++) {
            int idx = t + l * 256;
            int brow = idx >> 4, bcc = (idx & 15) * 8;
            const float* src = pw + (size_t)(d0 + brow) * 65536 + k0g + bcc;
            float4 v0 = *(const float4*)src;
            float4 v1 = *(const float4*)(src + 4);
            uint4 H, L;
            split8(v0, v1, H, L);
            *(uint4*)&Bh[brow][bcc] = H;
            *(uint4*)&Bl[brow][bcc] = L;
        }
        __syncthreads();
#pragma unroll
        for (int ks = 0; ks < 2; ks++) {
            uint32_t ah[4][4], al2[4][4], bh[4][2], bl2[4][2];
#pragma unroll
            for (int mt = 0; mt < 4; mt++) {
                int r = wm * 64 + mt * 16 + (lane & 15);
                int kc = ks * 16 + (lane >> 4) * 8;
                ldsm4(ah[mt], smem_u32(&Ah[r][kc]));
                ldsm4(al2[mt], smem_u32(&Al[r][kc]));
            }
#pragma unroll
            for (int nt = 0; nt < 4; nt++) {
                int kr = ks * 16 + (lane & 15);
                int col = wn * 32 + nt * 8;
                ldsm2t(bh[nt], smem_u32(&Bh[kr][col]));
                ldsm2t(bl2[nt], smem_u32(&Bl[kr][col]));
            }
#pragma unroll
            for (int mt = 0; mt < 4; mt++)
#pragma unroll
                for (int nt = 0; nt < 4; nt++) {
                    mma_bf16(c[mt][nt], ah[mt], bh[nt]);
                    mma_bf16(c[mt][nt], ah[mt], bl2[nt]);
                    mma_bf16(c[mt][nt], al2[mt], bh[nt]);
                }
        }
        __syncthreads();
    }
#pragma unroll
    for (int mt = 0; mt < 4; mt++)
#pragma unroll
        for (int h = 0; h < 2; h++) {
            int cs = wm * 64 + mt * 16 + gid + h * 8;
#pragma unroll
            for (int nt = 0; nt < 4; nt++) {
                int col = wn * 32 + nt * 8 + 2 * tig;
                float v0 = c[mt][nt][h * 2 + 0];
                float v1 = c[mt][nt][h * 2 + 1];
                __nv_bfloat16 h0 = __float2bfloat16(v0);
                __nv_bfloat16 h1 = __float2bfloat16(v1);
                __nv_bfloat162 H, L;
                H.x = h0; H.y = h1;
                L.x = __float2bfloat16(v0 - __bfloat162float(h0));
                L.y = __float2bfloat16(v1 - __bfloat162float(h1));
                *(__nv_bfloat162*)(g_w2h + (size_t)cs * 65536 + k0g + col) = H;
                *(__nv_bfloat162*)(g_w2l + (size_t)cs * 65536 + k0g + col) = L;
            }
        }
}

// ------------------- Kqb: qbias = pe_b @ wq; Kq0: init q --------------------
__global__ void kqb(const float* __restrict__ peb, const float* __restrict__ wq) {
    int c = threadIdx.x;   // 128
    float s = 0.f;
    for (int d = 0; d < 256; d++) s = fmaf(peb[d], wq[d * 128 + c], s);
    g_qbias[c] = s;
}
__global__ void kq0() {
    int i = blockIdx.x * 256 + threadIdx.x;   // 784*256 = 200704
    g_q[i] = g_qbias[i & 127];
}

// --------------------- K1: mask conv1x1 + BN1 stats (mma) -------------------
__global__ __launch_bounds__(256) void k1_maskconv(const float* __restrict__ dec,
                                                   const float* __restrict__ bias) {
    __shared__ __nv_bfloat16 Ah[128][40], Al[128][40];
    __shared__ __nv_bfloat16 Bh[32][136], Bl[32][136];
    __shared__ float ssum[128], ssq[128];
    int b = blockIdx.y;
    int pix0 = blockIdx.x * 128;
    int t = threadIdx.x;
    int wid = t >> 5, lane = t & 31;
    int wm = wid >> 2, wn = wid & 3;
    int gid = lane >> 2, tig = lane & 3;
    float c[4][4][4];
#pragma unroll
    for (int i = 0; i < 4; i++)
#pragma unroll
        for (int j = 0; j < 4; j++)
#pragma unroll
            for (int r = 0; r < 4; r++) c[i][j][r] = 0.f;

    const float* decb = dec + (size_t)b * 256 * S2 + pix0;

    int arow[2], ac[2], brow[2], bc[2];
#pragma unroll
    for (int l = 0; l < 2; l++) {
        int idx = t + l * 256;
        arow[l] = idx >> 2; ac[l] = (idx & 3) * 8;
        brow[l] = idx >> 4; bc[l] = (idx & 15) * 8;
    }
    uint4 pah[2], pal[2];
    float4 pb0[2], pb1[2];
#pragma unroll
    for (int l = 0; l < 2; l++) {
        pah[l] = *(const uint4*)(g_wh + arow[l] * 256 + ac[l]);
        pal[l] = *(const uint4*)(g_wl + arow[l] * 256 + ac[l]);
        pb0[l] = *(const float4*)(decb + (size_t)brow[l] * S2 + bc[l]);
        pb1[l] = *(const float4*)(decb + (size_t)brow[l] * S2 + bc[l] + 4);
    }

    for (int k0 = 0; k0 < 256; k0 += 32) {
#pragma unroll
        for (int l = 0; l < 2; l++) {
            *(uint4*)&Ah[arow[l]][ac[l]] = pah[l];
            *(uint4*)&Al[arow[l]][ac[l]] = pal[l];
            uint4 H, L;
            split8(pb0[l], pb1[l], H, L);
            *(uint4*)&Bh[brow[l]][bc[l]] = H;
            *(uint4*)&Bl[brow[l]][bc[l]] = L;
        }
        __syncthreads();
        int kn = k0 + 32;
        if (kn < 256) {
#pragma unroll
            for (int l = 0; l < 2; l++) {
                pah[l] = *(const uint4*)(g_wh + arow[l] * 256 + kn + ac[l]);
                pal[l] = *(const uint4*)(g_wl + arow[l] * 256 + kn + ac[l]);
                pb0[l] = *(const float4*)(decb + (size_t)(kn + brow[l]) * S2 + bc[l]);
                pb1[l] = *(const float4*)(decb + (size_t)(kn + brow[l]) * S2 + bc[l] + 4);
            }
        }
#pragma unroll
        for (int ks = 0; ks < 2; ks++) {
            uint32_t ah[4][4], al2[4][4], bh[4][2], bl2[4][2];
#pragma unroll
            for (int mt = 0; mt < 4; mt++) {
                int r = wm * 64 + mt * 16 + (lane & 15);
                int kc = ks * 16 + (lane >> 4) * 8;
                ldsm4(ah[mt], smem_u32(&Ah[r][kc]));
                ldsm4(al2[mt], smem_u32(&Al[r][kc]));
            }
#pragma unroll
            for (int nt = 0; nt < 4; nt++) {
                int kr = ks * 16 + (lane & 15);
                int col = wn * 32 + nt * 8;
                ldsm2t(bh[nt], smem_u32(&Bh[kr][col]));
                ldsm2t(bl2[nt], smem_u32(&Bl[kr][col]));
            }
#pragma unroll
            for (int mt = 0; mt < 4; mt++)
#pragma unroll
                for (int nt = 0; nt < 4; nt++) {
                    mma_bf16(c[mt][nt], ah[mt], bh[nt]);
                    mma_bf16(c[mt][nt], ah[mt], bl2[nt]);
                    mma_bf16(c[mt][nt], al2[mt], bh[nt]);
                }
        }
        __syncthreads();
    }

    if (t < 128) { ssum[t] = 0.f; ssq[t] = 0.f; }
    __syncthreads();
    float* t1b = g_t1 + (size_t)b * 128 * S2 + pix0;
#pragma unroll
    for (int mt = 0; mt < 4; mt++)
#pragma unroll
        for (int h = 0; h < 2; h++) {
            int cs = wm * 64 + mt * 16 + gid + h * 8;
            float bv = bias[cs];
            float ps = 0.f, pq = 0.f;
#pragma unroll
            for (int nt = 0; nt < 4; nt++) {
                float v0 = c[mt][nt][h * 2 + 0] + bv;
                float v1 = c[mt][nt][h * 2 + 1] + bv;
                ps += v0 + v1; pq += v0 * v0 + v1 * v1;
                int col = wn * 32 + nt * 8 + 2 * tig;
                *(float2*)(t1b + (size_t)cs * S2 + col) = make_float2(v0, v1);
            }
            atomicAdd(&ssum[cs], ps);
            atomicAdd(&ssq[cs], pq);
        }
    __syncthreads();
    if (t < 128) {
        atomicAdd(&g_stats1[t], ssum[t]);
        atomicAdd(&g_stats1[128 + t], ssq[t]);
    }
}

// ------------- K2: q = patches @ W2^T (mma, split-K, atomics) ---------------
// C[token 128][c 128] per block, K-slice 2048 (8 ci), BK=32.
__global__ __launch_bounds__(256) void k2_q(const float* __restrict__ dec) {
    __shared__ __nv_bfloat16 Pah[128][40], Pal[128][40];
    __shared__ __nv_bfloat16 Wbh[128][40], Wbl[128][40];
    int n0 = blockIdx.x * 128;
    int kbase = blockIdx.y * 2048;
    int t = threadIdx.x;
    int wid = t >> 5, lane = t & 31;
    int wm = wid >> 2, wn = wid & 3;
    int gid = lane >> 2, tig = lane & 3;
    float c[4][4][4];
#pragma unroll
    for (int i = 0; i < 4; i++)
#pragma unroll
        for (int j = 0; j < 4; j++)
#pragma unroll
            for (int r = 0; r < 4; r++) c[i][j][r] = 0.f;

    size_t pbase[2]; int asm_r[2], asm_c[2]; bool avalid[2];
    int wrow[2], wc[2];
#pragma unroll
    for (int l = 0; l < 2; l++) {
        int idx = t + l * 256;
        int nl = idx >> 2, part = idx & 3;
        int kyo = part >> 1, kx8 = (part & 1) * 8;
        int n = n0 + nl;
        avalid[l] = n < NTOK;
        int bb = avalid[l] ? n / 196 : 0;
        int rr = avalid[l] ? n % 196 : 0;
        int ph = rr / 14, pwv = rr % 14;
        pbase[l] = (size_t)bb * 256 * S2 + (size_t)(16 * ph + kyo) * 224 + 16 * pwv + kx8;
        asm_r[l] = nl; asm_c[l] = kyo * 16 + kx8;
        wrow[l] = idx >> 2; wc[l] = (idx & 3) * 8;
    }

    float4 pa0[2], pa1[2];
    uint4 pbh[2], pbl[2];
    {
        int k0 = kbase;
        int ci = k0 >> 8, ky = (k0 >> 4) & 15;
#pragma unroll
        for (int l = 0; l < 2; l++) {
            float4 z = make_float4(0.f, 0.f, 0.f, 0.f);
            pa0[l] = z; pa1[l] = z;
            if (avalid[l]) {
                size_t e = pbase[l] + (size_t)ci * S2 + ky * 224;
                pa0[l] = *(const float4*)(dec + e);
                pa1[l] = *(const float4*)(dec + e + 4);
            }
            pbh[l] = *(const uint4*)(g_w2h + (size_t)wrow[l] * 65536 + k0 + wc[l]);
            pbl[l] = *(const uint4*)(g_w2l + (size_t)wrow[l] * 65536 + k0 + wc[l]);
        }
    }

    for (int kc = 0; kc < 2048; kc += 32) {
#pragma unroll
        for (int l = 0; l < 2; l++) {
            uint4 H, L;
            split8(pa0[l], pa1[l], H, L);
            *(uint4*)&Pah[asm_r[l]][asm_c[l]] = H;
            *(uint4*)&Pal[asm_r[l]][asm_c[l]] = L;
            *(uint4*)&Wbh[wrow[l]][wc[l]] = pbh[l];
            *(uint4*)&Wbl[wrow[l]][wc[l]] = pbl[l];
        }
        __syncthreads();
        int kcn = kc + 32;
        if (kcn < 2048) {
            int k0 = kbase + kcn;
            int ci = k0 >> 8, ky = (k0 >> 4) & 15;
#pragma unroll
            for (int l = 0; l < 2; l++) {
                if (avalid[l]) {
                    size_t e = pbase[l] + (size_t)ci * S2 + ky * 224;
                    pa0[l] = *(const float4*)(dec + e);
                    pa1[l] = *(const float4*)(dec + e + 4);
                }
                pbh[l] = *(const uint4*)(g_w2h + (size_t)wrow[l] * 65536 + k0 + wc[l]);
                pbl[l] = *(const uint4*)(g_w2l + (size_t)wrow[l] * 65536 + k0 + wc[l]);
            }
        }
#pragma unroll
        for (int ks = 0; ks < 2; ks++) {
            int kk = ks * 16;
            uint32_t ah[4][4], al2[4][4], bh[4][2], bl2[4][2];
#pragma unroll
            for (int mt = 0; mt < 4; mt++) {
                int r = wm * 64 + mt * 16 + gid;
                ah[mt][0] = *(const uint32_t*)&Pah[r][kk + 2 * tig];
                ah[mt][1] = *(const uint32_t*)&Pah[r + 8][kk + 2 * tig];
                ah[mt][2] = *(const uint32_t*)&Pah[r][kk + 2 * tig + 8];
                ah[mt][3] = *(const uint32_t*)&Pah[r + 8][kk + 2 * tig + 8];
                al2[mt][0] = *(const uint32_t*)&Pal[r][kk + 2 * tig];
                al2[mt][1] = *(const uint32_t*)&Pal[r + 8][kk + 2 * tig];
                al2[mt][2] = *(const uint32_t*)&Pal[r][kk + 2 * tig + 8];
                al2[mt][3] = *(const uint32_t*)&Pal[r + 8][kk + 2 * tig + 8];
            }
#pragma unroll
            for (int nt = 0; nt < 4; nt++) {
                int cr = wn * 32 + nt * 8 + gid;
                bh[nt][0] = *(const uint32_t*)&Wbh[cr][kk + 2 * tig];
                bh[nt][1] = *(const uint32_t*)&Wbh[cr][kk + 2 * tig + 8];
                bl2[nt][0] = *(const uint32_t*)&Wbl[cr][kk + 2 * tig];
                bl2[nt][1] = *(const uint32_t*)&Wbl[cr][kk + 2 * tig + 8];
            }
#pragma unroll
            for (int mt = 0; mt < 4; mt++)
#pragma unroll
                for (int nt = 0; nt < 4; nt++) {
                    mma_bf16(c[mt][nt], ah[mt], bh[nt]);
                    mma_bf16(c[mt][nt], ah[mt], bl2[nt]);
                    mma_bf16(c[mt][nt], al2[mt], bh[nt]);
                }
        }
        __syncthreads();
    }
#pragma unroll
    for (int mt = 0; mt < 4; mt++)
#pragma unroll
        for (int h = 0; h < 2; h++) {
            int tok = n0 + wm * 64 + mt * 16 + gid + h * 8;
            if (tok < NTOK) {
#pragma unroll
                for (int nt = 0; nt < 4; nt++) {
                    int co = wn * 32 + nt * 8 + 2 * tig;
                    atomicAdd(&g_q[(size_t)tok * 128 + co], c[mt][nt][h * 2]);
                    atomicAdd(&g_q[(size_t)tok * 128 + co + 1], c[mt][nt][h * 2 + 1]);
                }
            }
        }
}

// --------------------------- K3: BN1 finalize -------------------------------
__global__ void k3_bn1(const float* __restrict__ g1, const float* __restrict__ b1) {
    int c = threadIdx.x;
    const float cnt = 401408.f;
    float m = g_stats1[c] / cnt;
    float var = g_stats1[128 + c] / cnt - m * m;
    float a = g1[c] * rsqrtf(var + 1e-5f);
    g_bnp1[c] = a;
    g_bnp1[128 + c] = b1[c] - m * a;
}

// ------------------------------ K4: k, v ------------------------------------
__global__ void k4_kv(const float* __restrict__ trans, const float* __restrict__ wk,
                      const float* __restrict__ wv) {
    __shared__ float rows[8][960];
    int b = blockIdx.y, ng = blockIdx.x, t = threadIdx.x;
    int nb = ng * 8;
    int nr = 196 - nb; if (nr > 8) nr = 8;
    for (int i = t; i < nr * 960; i += 128) {
        int rr = i / 960, e = i % 960;
        rows[rr][e] = trans[((size_t)(b * 196) + nb + rr) * 960 + e];
    }
    __syncthreads();
    float ak[8] = {}, av[8] = {};
    for (int e = 0; e < 960; e++) {
        float wkv = wk[e * 128 + t], wvv = wv[e * 128 + t];
#pragma unroll
        for (int rr = 0; rr < 8; rr++) {
            ak[rr] = fmaf(rows[rr][e], wkv, ak[rr]);
            av[rr] = fmaf(rows[rr][e], wvv, av[rr]);
        }
    }
    for (int rr = 0; rr < nr; rr++) {
        g_k[((size_t)(b * 196) + nb + rr) * 128 + t] = ak[rr];
        g_v[((size_t)(b * 196) + nb + rr) * 128 + t] = av[rr];
    }
}

// -------------------- K5: sim = q^T k + instance-norm stats ------------------
__global__ __launch_bounds__(256) void k5_sim() {
    __shared__ float Qs[16][128], Ks[16][128];
    __shared__ float red[256];
    int b = blockIdx.x;
    int t = threadIdx.x, tx = t & 15, ty = t >> 4;
    float acc[8][8] = {};
    const float* qb = g_q + (size_t)b * 196 * 128;
    const float* kb = g_k + (size_t)b * 196 * 128;
    for (int n0 = 0; n0 < 196; n0 += 16) {
        int nc = 196 - n0; if (nc > 16) nc = 16;
#pragma unroll
        for (int l = 0; l < 2; l++) {
            int j = t + l * 256;
            int kk = j >> 5, c4 = (j & 31) * 4;
            float4 qv = make_float4(0.f, 0.f, 0.f, 0.f), kv = qv;
            if (kk < nc) {
                qv = *(const float4*)(qb + (size_t)(n0 + kk) * 128 + c4);
                kv = *(const float4*)(kb + (size_t)(n0 + kk) * 128 + c4);
            }
            *(float4*)&Qs[kk][c4] = qv;
            *(float4*)&Ks[kk][c4] = kv;
        }
        __syncthreads();
#pragma unroll
        for (int k = 0; k < 16; k++) {
            float a[8], bb[8];
#pragma unroll
            for (int i = 0; i < 8; i++) a[i] = Qs[k][ty * 8 + i];
#pragma unroll
            for (int j = 0; j < 8; j++) bb[j] = Ks[k][tx * 8 + j];
#pragma unroll
            for (int i = 0; i < 8; i++)
#pragma unroll
                for (int j = 0; j < 8; j++)
                    acc[i][j] = fmaf(a[i], bb[j], acc[i][j]);
        }
        __syncthreads();
    }
    float s = 0.f, q = 0.f;
#pragma unroll
    for (int i = 0; i < 8; i++)
#pragma unroll
        for (int j = 0; j < 8; j++) {
            float v = acc[i][j];
            s += v; q += v * v;
            g_sim[((size_t)b * 128 + ty * 8 + i) * 128 + tx * 8 + j] = v;
        }
    red[t] = s; __syncthreads();
    for (int o = 128; o > 0; o >>= 1) { if (t < o) red[t] += red[t + o]; __syncthreads(); }
    float ssum = red[0]; __syncthreads();
    red[t] = q; __syncthreads();
    for (int o = 128; o > 0; o >>= 1) { if (t < o) red[t] += red[t + o]; __syncthreads(); }
    if (t == 0) {
        float m = ssum / 16384.f;
        float var = red[0] / 16384.f - m * m;
        g_inorm[b * 2] = m;
        g_inorm[b * 2 + 1] = rsqrtf(var + 1e-5f);
    }
}

// ------------------------- K5c: row softmax ---------------------------------
__global__ void k5c_soft() {
    int c = blockIdx.x, b = blockIdx.y, t = threadIdx.x;
    __shared__ float red[4], red2[4];
    float m = g_inorm[b * 2], rs = g_inorm[b * 2 + 1];
    float v = (g_sim[((size_t)b * 128 + c) * 128 + t] - m) * rs;
    float mx = v;
#pragma unroll
    for (int o = 16; o > 0; o >>= 1) mx = fmaxf(mx, __shfl_xor_sync(0xffffffffu, mx, o));
    if ((t & 31) == 0) red[t >> 5] = mx;
    __syncthreads();
    mx = fmaxf(fmaxf(red[0], red[1]), fmaxf(red[2], red[3]));
    float e = expf(v - mx);
    float s = e;
#pragma unroll
    for (int o = 16; o > 0; o >>= 1) s += __shfl_xor_sync(0xffffffffu, s, o);
    if ((t & 31) == 0) red2[t >> 5] = s;
    __syncthreads();
    s = red2[0] + red2[1] + red2[2] + red2[3];
    g_p[((size_t)b * 128 + c) * 128 + t] = e / s;
}

// ------------------------ K5b: o = P v ; o2 = o wo ---------------------------
__global__ void k5b_o(const float* __restrict__ wo) {
    int n = blockIdx.x, b = blockIdx.y, t = threadIdx.x;
    __shared__ float vrow[128], orow[128];
    vrow[t] = g_v[((size_t)(b * 196) + n) * 128 + t];
    __syncthreads();
    const float* pb = g_p + (size_t)b * 128 * 128;
    float o = 0.f;
    for (int d = 0; d < 128; d++) o = fmaf(pb[t * 128 + d], vrow[d], o);
    orow[t] = o;
    __syncthreads();
    float o2 = 0.f;
    for (int c = 0; c < 128; c++) o2 = fmaf(orow[c], wo[c * 128 + t], o2);
    g_o2[((size_t)(b * 196) + n) * 128 + t] = o2;
}

// --------------------------- K6: reconstruct conv ----------------------------
__global__ void k6_rec(const float* __restrict__ rw, const float* __restrict__ rb) {
    int n = blockIdx.x, b = blockIdx.y, t = threadIdx.x;
    __shared__ float xrow[128];
    xrow[t] = g_o2[((size_t)(b * 196) + n) * 128 + t];
    __syncthreads();
    float y = rb[t];
    for (int ci = 0; ci < 128; ci++) y = fmaf(rw[t * 128 + ci], xrow[ci], y);
    g_y[((size_t)(b * 128 + t)) * 196 + n] = y;
}

// ------------------------ K7: BN2 stats + finalize ---------------------------
__global__ void k7_bn2(const float* __restrict__ g2, const float* __restrict__ b2) {
    int co = blockIdx.x, t = threadIdx.x;
    __shared__ float rs[256], rq[256];
    float s = 0.f, q = 0.f;
    for (int i = t; i < 1568; i += 256) {
        float v = g_y[((size_t)((i / 196) * 128 + co)) * 196 + (i % 196)];
        s += v; q += v * v;
    }
    rs[t] = s; rq[t] = q; __syncthreads();
    for (int o = 128; o > 0; o >>= 1) {
        if (t < o) { rs[t] += rs[t + o]; rq[t] += rq[t + o]; }
        __syncthreads();
    }
    if (t == 0) {
        float m = rs[0] / 1568.f;
        float var = rq[0] / 1568.f - m * m;
        float a = g2[co] * rsqrtf(var + 1e-5f);
        g_bnp2[co] = a;
        g_bnp2[128 + co] = b2[co] - m * a;
    }
}

// ------------------------------ K8: fused epilogue ---------------------------
__global__ void k8_final(float* __restrict__ out) {
    size_t i4 = (size_t)blockIdx.x * 256 + threadIdx.x;
    int x4 = (int)(i4 % 56);
    size_t r = i4 / 56;
    int y = (int)(r % 224);
    size_t r2 = r / 224;
    int c = (int)(r2 % 128);
    int b = (int)(r2 / 128);
    float4 tv = *(const float4*)(g_t1 + i4 * 4);
    float a1 = g_bnp1[c], b1 = g_bnp1[128 + c];
    float a2 = g_bnp2[c], b2 = g_bnp2[128 + c];
    int n = (y >> 4) * 14 + (x4 >> 2);
    float z = fmaxf(fmaf(a2, g_y[((size_t)(b * 128 + c)) * 196 + n], b2), 0.f);
    float4 o;
    o.x = fmaxf(fmaf(a1, tv.x, b1), 0.f) * z;
    o.y = fmaxf(fmaf(a1, tv.y, b1), 0.f) * z;
    o.z = fmaxf(fmaf(a1, tv.z, b1), 0.f) * z;
    o.w = fmaxf(fmaf(a1, tv.w, b1), 0.f) * z;
    *(float4*)(out + i4 * 4) = o;
}

// ---------------------------------------------------------------------------
extern "C" void kernel_launch(void* const* d_in, const int* in_sizes, int n_in,
                              void* d_out, int out_size) {
    const float* decoder = (const float*)d_in[0];
    const float* trans   = (const float*)d_in[1];
    const float* pe_w    = (const float*)d_in[2];
    const float* pe_b    = (const float*)d_in[3];
    const float* convm_w = (const float*)d_in[4];
    const float* convm_b = (const float*)d_in[5];
    const float* bn1_g   = (const float*)d_in[6];
    const float* bn1_b   = (const float*)d_in[7];
    const float* wq      = (const float*)d_in[8];
    const float* wk      = (const float*)d_in[9];
    const float* wv      = (const float*)d_in[10];
    const float* wo      = (const float*)d_in[11];
    const float* rec_w   = (const float*)d_in[12];
    const float* rec_b   = (const float*)d_in[13];
    const float* bn2_g   = (const float*)d_in[14];
    const float* bn2_b   = (const float*)d_in[15];
    float* out = (float*)d_out;

    __nv_bfloat16 *p_wh, *p_wl;
    cudaGetSymbolAddress((void**)&p_wh, g_wh);
    cudaGetSymbolAddress((void**)&p_wl, g_wl);

    kc_split<<<16, 256>>>(convm_w, p_wh, p_wl);       // convm_w 32768 elems
    kw_w2<<<512, 256>>>(pe_w, wq);                    // W2 = pe_w^T wq (bf16 hi/lo)
    kqb<<<1, 128>>>(pe_b, wq);
    kq0<<<784, 256>>>();
    k0_zero<<<1, 256>>>();
    k1_maskconv<<<dim3(392, 8), 256>>>(decoder, convm_b);
    k2_q<<<dim3(13, 32), 256>>>(decoder);
    k3_bn1<<<1, 128>>>(bn1_g, bn1_b);
    k4_kv<<<dim3(25, 8), 128>>>(trans, wk, wv);
    k5_sim<<<8, 256>>>();
    k5c_soft<<<dim3(128, 8), 128>>>();
    k5b_o<<<dim3(196, 8), 128>>>(wo);
    k6_rec<<<dim3(196, 8), 128>>>(rec_w, rec_b);
    k7_bn2<<<128, 256>>>(bn2_g, bn2_b);
    k8_final<<<50176, 256>>>(out);
}